// round 2
// baseline (speedup 1.0000x reference)
#include <cuda_runtime.h>

// Problem constants
#define NB_MAX 2048
#define TT 64
#define DD 384
#define NH 8
#define HS 48
#define FFDIM 1536

// Padded shared strides (floats) - chosen so (stride*row + col) % 32 banks differ per row
#define HSTR 388   // h / h2 buffer stride
#define QSTR 52    // q/k/v/attnout stride
#define SSTR 68    // probs stride
#define RSTR 132   // FF relu buffer stride
#define NTHR 512
#define CHUNK_D 64

typedef unsigned long long u64;

__device__ __forceinline__ u64 pack2(float lo, float hi) {
    u64 r; asm("mov.b64 %0, {%1, %2};" : "=l"(r) : "f"(lo), "f"(hi)); return r;
}
__device__ __forceinline__ u64 bc2(float v) { return pack2(v, v); }
__device__ __forceinline__ float2 unp2(u64 v) {
    float2 f; asm("mov.b64 {%0, %1}, %2;" : "=f"(f.x), "=f"(f.y) : "l"(v)); return f;
}
// packed fp32x2 FMA (Blackwell): 2 FP32 FMAs per instruction
__device__ __forceinline__ u64 fma2(u64 a, u64 b, u64 c) {
    u64 d; asm("fma.rn.f32x2 %0, %1, %2, %3;" : "=l"(d) : "l"(a), "l"(b), "l"(c)); return d;
}

// Shared memory layout (floats)
#define OFF_H    0
#define OFF_Q    (OFF_H + TT*HSTR)
#define OFF_K    (OFF_Q + TT*QSTR)
#define OFF_V    (OFF_K + TT*QSTR)
#define OFF_S    (OFF_V + TT*QSTR)
#define OFF_RED  (OFF_S + TT*SSTR)
#define OFF_W    (OFF_RED + TT*16)
#define SMEM_FLOATS (OFF_W + CHUNK_D*144)

__global__ void __launch_bounds__(NTHR, 1)
block_kernel(const float* __restrict__ x,
             const float* __restrict__ wq, const float* __restrict__ bq,
             const float* __restrict__ wk, const float* __restrict__ bk,
             const float* __restrict__ wv, const float* __restrict__ bvv,
             const float* __restrict__ wo, const float* __restrict__ bo,
             const float* __restrict__ w1, const float* __restrict__ b1,
             const float* __restrict__ w2, const float* __restrict__ b2,
             const float* __restrict__ g1, const float* __restrict__ be1,
             const float* __restrict__ g2, const float* __restrict__ be2,
             float* __restrict__ out)
{
    extern __shared__ float sm[];
    float* sH   = sm + OFF_H;
    float* sQ   = sm + OFF_Q;
    float* sK   = sm + OFF_K;
    float* sV   = sm + OFF_V;
    float* sS   = sm + OFF_S;
    float* sRed = sm + OFF_RED;
    float* sW   = sm + OFF_W;
    float* sR   = sm + OFF_Q;   // FF relu buffer reuses q/k/v/probs region

    const int tid = threadIdx.x;
    const int b   = blockIdx.x;
    const int w   = tid >> 5;   // warp id 0..15
    const int l   = tid & 31;   // lane
    const int t0  = tid >> 3;   // row 0..63 (group layout)
    const int g   = tid & 7;    // group 0..7
    const int e6  = g * 6;      // head-dim slice start

    // ================= LN1: x -> sH =================
    {
        const float* xb = x + (size_t)b * TT * DD;
        float xv[4][12];
        #pragma unroll
        for (int rr = 0; rr < 4; rr++) {
            const int r = 4*w + rr;
            float s1 = 0.f, s2 = 0.f;
            #pragma unroll
            for (int jt = 0; jt < 3; jt++) {
                float4 v = *(const float4*)(xb + r*DD + jt*128 + 4*l);
                xv[rr][4*jt+0] = v.x; xv[rr][4*jt+1] = v.y;
                xv[rr][4*jt+2] = v.z; xv[rr][4*jt+3] = v.w;
            }
            #pragma unroll
            for (int i = 0; i < 12; i++) { s1 += xv[rr][i]; s2 += xv[rr][i]*xv[rr][i]; }
            #pragma unroll
            for (int o = 16; o > 0; o >>= 1) {
                s1 += __shfl_xor_sync(0xffffffffu, s1, o);
                s2 += __shfl_xor_sync(0xffffffffu, s2, o);
            }
            const float mean = s1 * (1.0f/384.0f);
            const float var  = s2 * (1.0f/384.0f) - mean*mean;
            const float rstd = rsqrtf(var + 1e-5f);
            #pragma unroll
            for (int jt = 0; jt < 3; jt++) {
                const int c = jt*128 + 4*l;
                float4 gg = *(const float4*)(g1 + c);
                float4 bb = *(const float4*)(be1 + c);
                float4 o4;
                o4.x = (xv[rr][4*jt+0]-mean)*rstd*gg.x + bb.x;
                o4.y = (xv[rr][4*jt+1]-mean)*rstd*gg.y + bb.y;
                o4.z = (xv[rr][4*jt+2]-mean)*rstd*gg.z + bb.z;
                o4.w = (xv[rr][4*jt+3]-mean)*rstd*gg.w + bb.w;
                *(float4*)(sH + r*HSTR + c) = o4;
            }
        }
    }
    __syncthreads();

    // ========== attention: register accumulator = attn@wo + bo ==========
    // layout: acc[rr][jt][p] covers row 4w+rr, cols jt*128 + 4l + {2p, 2p+1}
    u64 acc[4][3][2];
    #pragma unroll
    for (int jt = 0; jt < 3; jt++) {
        float4 bv4 = *(const float4*)(bo + jt*128 + 4*l);
        u64 p0 = pack2(bv4.x, bv4.y), p1 = pack2(bv4.z, bv4.w);
        #pragma unroll
        for (int rr = 0; rr < 4; rr++) { acc[rr][jt][0] = p0; acc[rr][jt][1] = p1; }
    }

    const float kScale = 0.14433756729740643f; // 48^-0.5

    for (int h = 0; h < NH; h++) {
        // ---- q,k,v generation: thread (t0, e6..e6+5) for each matrix ----
        u64 qa[3], ka[3], va[3];
        #pragma unroll
        for (int p = 0; p < 3; p++) {
            qa[p] = pack2(bq [h*HS + e6 + 2*p], bq [h*HS + e6 + 2*p + 1]);
            ka[p] = pack2(bk [h*HS + e6 + 2*p], bk [h*HS + e6 + 2*p + 1]);
            va[p] = pack2(bvv[h*HS + e6 + 2*p], bvv[h*HS + e6 + 2*p + 1]);
        }
        for (int c0 = 0; c0 < DD; c0 += CHUNK_D) {
            __syncthreads();
            // stage wq/wk/wv chunk [CHUNK_D x 48 each] into sW (144 floats per d)
            {
                const int nf4 = CHUNK_D * 144 / 4; // 2304
                for (int i = tid; i < nf4; i += NTHR) {
                    const int dl  = i / 36;
                    const int rem = i - dl*36;
                    const int m   = rem / 12;
                    const int e4  = rem - m*12;
                    const float* src = (m == 0) ? wq : ((m == 1) ? wk : wv);
                    float4 v = *(const float4*)(src + ((size_t)(h*DD + c0 + dl))*HS + e4*4);
                    *(float4*)(sW + dl*144 + m*48 + e4*4) = v;
                }
            }
            __syncthreads();
            #pragma unroll 4
            for (int dl = 0; dl < CHUNK_D; dl++) {
                const u64 hv = bc2(sH[t0*HSTR + c0 + dl]);
                const float* wrow = sW + dl*144 + e6;
                #pragma unroll
                for (int p = 0; p < 3; p++) {
                    qa[p] = fma2(hv, *(const u64*)(wrow +       2*p), qa[p]);
                    ka[p] = fma2(hv, *(const u64*)(wrow + 48  + 2*p), ka[p]);
                    va[p] = fma2(hv, *(const u64*)(wrow + 96  + 2*p), va[p]);
                }
            }
        }
        // write q,k,v to padded smem
        #pragma unroll
        for (int p = 0; p < 3; p++) {
            float2 f;
            f = unp2(qa[p]); sQ[t0*QSTR + e6 + 2*p] = f.x; sQ[t0*QSTR + e6 + 2*p + 1] = f.y;
            f = unp2(ka[p]); sK[t0*QSTR + e6 + 2*p] = f.x; sK[t0*QSTR + e6 + 2*p + 1] = f.y;
            f = unp2(va[p]); sV[t0*QSTR + e6 + 2*p] = f.x; sV[t0*QSTR + e6 + 2*p + 1] = f.y;
        }
        __syncthreads();

        // ---- scores + causal softmax: thread (t0) owns cols s = g + 8k ----
        float sc[8];
        float mx = -1e30f;
        #pragma unroll
        for (int kk = 0; kk < 8; kk++) {
            const int s = g + 8*kk;
            float val = -1e30f;
            if (s <= t0) {
                u64 a = 0ull;
                const float* qrow = sQ + t0*QSTR;
                const float* krow = sK + s*QSTR;
                #pragma unroll
                for (int i = 0; i < 24; i++)
                    a = fma2(*(const u64*)(qrow + 2*i), *(const u64*)(krow + 2*i), a);
                float2 f = unp2(a);
                val = (f.x + f.y) * kScale;
                mx = fmaxf(mx, val);
            }
            sc[kk] = val;
        }
        sRed[t0*16 + g] = mx;
        __syncthreads();
        float rmx = sRed[t0*16];
        #pragma unroll
        for (int i = 1; i < 8; i++) rmx = fmaxf(rmx, sRed[t0*16 + i]);
        float lsum = 0.f;
        #pragma unroll
        for (int kk = 0; kk < 8; kk++) {
            const int s = g + 8*kk;
            const float e = (s <= t0) ? __expf(sc[kk] - rmx) : 0.f;
            sc[kk] = e;
            lsum += e;
        }
        sRed[t0*16 + 8 + g] = lsum;
        __syncthreads();
        float rsum = 0.f;
        #pragma unroll
        for (int i = 0; i < 8; i++) rsum += sRed[t0*16 + 8 + i];
        const float inv = 1.0f / rsum;
        #pragma unroll
        for (int kk = 0; kk < 8; kk++) sS[t0*SSTR + g + 8*kk] = sc[kk] * inv;
        __syncthreads();

        // ---- attnout[t0][e6..e6+5] = probs @ v ----
        u64 oa[3] = {0ull, 0ull, 0ull};
        for (int s = 0; s < TT; s++) {
            const u64 p = bc2(sS[t0*SSTR + s]);
            const float* vrow = sV + s*QSTR + e6;
            #pragma unroll
            for (int i = 0; i < 3; i++)
                oa[i] = fma2(p, *(const u64*)(vrow + 2*i), oa[i]);
        }
        #pragma unroll
        for (int p = 0; p < 3; p++) {
            float2 f = unp2(oa[p]);
            sQ[t0*QSTR + e6 + 2*p] = f.x;   // overwrite q (done with it)
            sQ[t0*QSTR + e6 + 2*p + 1] = f.y;
        }
        __syncthreads();

        // ---- wo projection accumulate (warp layout, 4-row weight reuse) ----
        {
            const float* wobase = wo + (size_t)(h*HS)*DD + 4*l;
            #pragma unroll 2
            for (int c = 0; c < HS; c++) {
                u64 av[4];
                #pragma unroll
                for (int rr = 0; rr < 4; rr++) av[rr] = bc2(sQ[(4*w+rr)*QSTR + c]);
                const float* wrow = wobase + (size_t)c*DD;
                #pragma unroll
                for (int jt = 0; jt < 3; jt++) {
                    float4 wv4 = *(const float4*)(wrow + jt*128);
                    u64 wp0 = pack2(wv4.x, wv4.y), wp1 = pack2(wv4.z, wv4.w);
                    #pragma unroll
                    for (int rr = 0; rr < 4; rr++) {
                        acc[rr][jt][0] = fma2(av[rr], wp0, acc[rr][jt][0]);
                        acc[rr][jt][1] = fma2(av[rr], wp1, acc[rr][jt][1]);
                    }
                }
            }
        }
    } // heads

    // ========== residual + LN2, re-init acc = h2 + b2 ==========
    __syncthreads();
    {
        #pragma unroll
        for (int rr = 0; rr < 4; rr++) {
            const int r = 4*w + rr;
            float hv[12];
            float s1 = 0.f, s2 = 0.f;
            #pragma unroll
            for (int jt = 0; jt < 3; jt++) {
                const int c = jt*128 + 4*l;
                float2 a0 = unp2(acc[rr][jt][0]);
                float2 a1 = unp2(acc[rr][jt][1]);
                hv[4*jt+0] = sH[r*HSTR + c + 0] + a0.x;
                hv[4*jt+1] = sH[r*HSTR + c + 1] + a0.y;
                hv[4*jt+2] = sH[r*HSTR + c + 2] + a1.x;
                hv[4*jt+3] = sH[r*HSTR + c + 3] + a1.y;
            }
            #pragma unroll
            for (int i = 0; i < 12; i++) { s1 += hv[i]; s2 += hv[i]*hv[i]; }
            #pragma unroll
            for (int o = 16; o > 0; o >>= 1) {
                s1 += __shfl_xor_sync(0xffffffffu, s1, o);
                s2 += __shfl_xor_sync(0xffffffffu, s2, o);
            }
            const float mean = s1 * (1.0f/384.0f);
            const float var  = s2 * (1.0f/384.0f) - mean*mean;
            const float rstd = rsqrtf(var + 1e-5f);
            #pragma unroll
            for (int jt = 0; jt < 3; jt++) {
                const int c = jt*128 + 4*l;
                float4 gg  = *(const float4*)(g2 + c);
                float4 bb  = *(const float4*)(be2 + c);
                float4 b2v = *(const float4*)(b2 + c);
                float h0 = (hv[4*jt+0]-mean)*rstd*gg.x + bb.x;
                float h1 = (hv[4*jt+1]-mean)*rstd*gg.y + bb.y;
                float h2 = (hv[4*jt+2]-mean)*rstd*gg.z + bb.z;
                float h3 = (hv[4*jt+3]-mean)*rstd*gg.w + bb.w;
                *(float4*)(sH + r*HSTR + c) = make_float4(h0, h1, h2, h3);
                acc[rr][jt][0] = pack2(h0 + b2v.x, h1 + b2v.y);
                acc[rr][jt][1] = pack2(h2 + b2v.z, h3 + b2v.w);
            }
        }
    }
    __syncthreads();

    // ========== FF: out = h2 + relu(h2@w1 + b1)@w2 + b2 (12 chunks of 128) ==========
    for (int ch = 0; ch < 12; ch++) {
        // FF-a: r = relu(h2 @ w1[:, ch*128 + 4l..] + b1)
        u64 fa[4][2];
        {
            float4 b1v = *(const float4*)(b1 + ch*128 + 4*l);
            u64 p0 = pack2(b1v.x, b1v.y), p1 = pack2(b1v.z, b1v.w);
            #pragma unroll
            for (int rr = 0; rr < 4; rr++) { fa[rr][0] = p0; fa[rr][1] = p1; }
        }
        {
            const float* w1p = w1 + ch*128 + 4*l;
            #pragma unroll 2
            for (int d = 0; d < DD; d += 2) {
                float4 wa = *(const float4*)(w1p + (size_t)d*FFDIM);
                float4 wb = *(const float4*)(w1p + (size_t)(d+1)*FFDIM);
                u64 wa0 = pack2(wa.x, wa.y), wa1 = pack2(wa.z, wa.w);
                u64 wb0 = pack2(wb.x, wb.y), wb1 = pack2(wb.z, wb.w);
                #pragma unroll
                for (int rr = 0; rr < 4; rr++) {
                    float2 hp = *(const float2*)(sH + (4*w+rr)*HSTR + d);
                    u64 h0 = bc2(hp.x), h1 = bc2(hp.y);
                    fa[rr][0] = fma2(h0, wa0, fa[rr][0]);
                    fa[rr][1] = fma2(h0, wa1, fa[rr][1]);
                    fa[rr][0] = fma2(h1, wb0, fa[rr][0]);
                    fa[rr][1] = fma2(h1, wb1, fa[rr][1]);
                }
            }
        }
        #pragma unroll
        for (int rr = 0; rr < 4; rr++) {
            float2 f0 = unp2(fa[rr][0]), f1 = unp2(fa[rr][1]);
            *(float4*)(sR + (4*w+rr)*RSTR + 4*l) =
                make_float4(fmaxf(f0.x, 0.f), fmaxf(f0.y, 0.f),
                            fmaxf(f1.x, 0.f), fmaxf(f1.y, 0.f));
        }
        __syncthreads();

        // FF-b: acc += r @ w2[ch*128.., :]
        {
            const float* w2p = w2 + (size_t)(ch*128)*DD + 4*l;
            #pragma unroll 2
            for (int c = 0; c < 128; c++) {
                u64 rv[4];
                #pragma unroll
                for (int rr = 0; rr < 4; rr++) rv[rr] = bc2(sR[(4*w+rr)*RSTR + c]);
                const float* wrow = w2p + (size_t)c*DD;
                #pragma unroll
                for (int jt = 0; jt < 3; jt++) {
                    float4 wv4 = *(const float4*)(wrow + jt*128);
                    u64 wp0 = pack2(wv4.x, wv4.y), wp1 = pack2(wv4.z, wv4.w);
                    #pragma unroll
                    for (int rr = 0; rr < 4; rr++) {
                        acc[rr][jt][0] = fma2(rv[rr], wp0, acc[rr][jt][0]);
                        acc[rr][jt][1] = fma2(rv[rr], wp1, acc[rr][jt][1]);
                    }
                }
            }
        }
        __syncthreads();
    }

    // ========== store output ==========
    {
        float* ob = out + (size_t)b * TT * DD;
        #pragma unroll
        for (int rr = 0; rr < 4; rr++) {
            const int r = 4*w + rr;
            #pragma unroll
            for (int jt = 0; jt < 3; jt++) {
                float2 a0 = unp2(acc[rr][jt][0]);
                float2 a1 = unp2(acc[rr][jt][1]);
                *(float4*)(ob + r*DD + jt*128 + 4*l) = make_float4(a0.x, a0.y, a1.x, a1.y);
            }
        }
    }
}

extern "C" void kernel_launch(void* const* d_in, const int* in_sizes, int n_in,
                              void* d_out, int out_size) {
    const float* x   = (const float*)d_in[0];
    const float* wq  = (const float*)d_in[1];
    const float* bq  = (const float*)d_in[2];
    const float* wk  = (const float*)d_in[3];
    const float* bk  = (const float*)d_in[4];
    const float* wv  = (const float*)d_in[5];
    const float* bv  = (const float*)d_in[6];
    const float* wo  = (const float*)d_in[7];
    const float* bo  = (const float*)d_in[8];
    const float* w1  = (const float*)d_in[9];
    const float* b1  = (const float*)d_in[10];
    const float* w2  = (const float*)d_in[11];
    const float* b2  = (const float*)d_in[12];
    const float* g1  = (const float*)d_in[13];
    const float* be1 = (const float*)d_in[14];
    const float* g2  = (const float*)d_in[15];
    const float* be2 = (const float*)d_in[16];
    float* out = (float*)d_out;

    const int nb = in_sizes[0] / (TT * DD);
    const size_t smem = (size_t)SMEM_FLOATS * sizeof(float);

    cudaFuncSetAttribute(block_kernel, cudaFuncAttributeMaxDynamicSharedMemorySize, (int)smem);
    block_kernel<<<nb, NTHR, smem>>>(x, wq, bq, wk, bk, wv, bv, wo, bo,
                                     w1, b1, w2, b2, g1, be1, g2, be2, out);
}

// round 4
// speedup vs baseline: 1.0011x; 1.0011x over previous
#include <cuda_runtime.h>

// Problem constants
#define NB_MAX 2048
#define TT 64
#define DD 384
#define NH 8
#define HS 48
#define FFDIM 1536

// Padded shared strides (floats) - chosen so (stride*row + col) % 32 banks differ per row
#define HSTR 388   // h / h2 buffer stride
#define QSTR 52    // q/k/v/attnout stride
#define SSTR 68    // probs stride
#define RSTR 132   // FF relu buffer stride
#define NTHR 512
#define CHUNK_D 64

typedef unsigned long long u64;

__device__ __forceinline__ u64 pack2(float lo, float hi) {
    u64 r; asm("mov.b64 %0, {%1, %2};" : "=l"(r) : "f"(lo), "f"(hi)); return r;
}
__device__ __forceinline__ u64 bc2(float v) { return pack2(v, v); }
__device__ __forceinline__ float2 unp2(u64 v) {
    float2 f; asm("mov.b64 {%0, %1}, %2;" : "=f"(f.x), "=f"(f.y) : "l"(v)); return f;
}
// packed fp32x2 FMA (Blackwell): 2 FP32 FMAs per instruction
__device__ __forceinline__ u64 fma2(u64 a, u64 b, u64 c) {
    u64 d; asm("fma.rn.f32x2 %0, %1, %2, %3;" : "=l"(d) : "l"(a), "l"(b), "l"(c)); return d;
}

// Shared memory layout (floats)
#define OFF_H    0
#define OFF_Q    (OFF_H + TT*HSTR)
#define OFF_K    (OFF_Q + TT*QSTR)
#define OFF_V    (OFF_K + TT*QSTR)
#define OFF_S    (OFF_V + TT*QSTR)
#define OFF_RED  (OFF_S + TT*SSTR)
#define OFF_W    (OFF_RED + TT*16)
#define SMEM_FLOATS (OFF_W + CHUNK_D*144)

__global__ void __launch_bounds__(NTHR, 1)
block_kernel(const float* __restrict__ x,
             const float* __restrict__ wq, const float* __restrict__ bq,
             const float* __restrict__ wk, const float* __restrict__ bk,
             const float* __restrict__ wv, const float* __restrict__ bvv,
             const float* __restrict__ wo, const float* __restrict__ bo,
             const float* __restrict__ w1, const float* __restrict__ b1,
             const float* __restrict__ w2, const float* __restrict__ b2,
             const float* __restrict__ g1, const float* __restrict__ be1,
             const float* __restrict__ g2, const float* __restrict__ be2,
             float* __restrict__ out)
{
    extern __shared__ float sm[];
    float* sH   = sm + OFF_H;
    float* sQ   = sm + OFF_Q;
    float* sK   = sm + OFF_K;
    float* sV   = sm + OFF_V;
    float* sS   = sm + OFF_S;
    float* sRed = sm + OFF_RED;
    float* sW   = sm + OFF_W;
    float* sR   = sm + OFF_Q;   // FF relu buffer reuses q/k/v/probs region

    const int tid = threadIdx.x;
    const int b   = blockIdx.x;
    const int w   = tid >> 5;   // warp id 0..15
    const int l   = tid & 31;   // lane
    const int t0  = tid >> 3;   // row 0..63 (group layout)
    const int g   = tid & 7;    // group 0..7
    const int e6  = g * 6;      // head-dim slice start

    // ================= LN1: x -> sH =================
    {
        const float* xb = x + (size_t)b * TT * DD;
        float xv[4][12];
        #pragma unroll
        for (int rr = 0; rr < 4; rr++) {
            const int r = 4*w + rr;
            float s1 = 0.f, s2 = 0.f;
            #pragma unroll
            for (int jt = 0; jt < 3; jt++) {
                float4 v = *(const float4*)(xb + r*DD + jt*128 + 4*l);
                xv[rr][4*jt+0] = v.x; xv[rr][4*jt+1] = v.y;
                xv[rr][4*jt+2] = v.z; xv[rr][4*jt+3] = v.w;
            }
            #pragma unroll
            for (int i = 0; i < 12; i++) { s1 += xv[rr][i]; s2 += xv[rr][i]*xv[rr][i]; }
            #pragma unroll
            for (int o = 16; o > 0; o >>= 1) {
                s1 += __shfl_xor_sync(0xffffffffu, s1, o);
                s2 += __shfl_xor_sync(0xffffffffu, s2, o);
            }
            const float mean = s1 * (1.0f/384.0f);
            const float var  = s2 * (1.0f/384.0f) - mean*mean;
            const float rstd = rsqrtf(var + 1e-5f);
            #pragma unroll
            for (int jt = 0; jt < 3; jt++) {
                const int c = jt*128 + 4*l;
                float4 gg = *(const float4*)(g1 + c);
                float4 bb = *(const float4*)(be1 + c);
                float4 o4;
                o4.x = (xv[rr][4*jt+0]-mean)*rstd*gg.x + bb.x;
                o4.y = (xv[rr][4*jt+1]-mean)*rstd*gg.y + bb.y;
                o4.z = (xv[rr][4*jt+2]-mean)*rstd*gg.z + bb.z;
                o4.w = (xv[rr][4*jt+3]-mean)*rstd*gg.w + bb.w;
                *(float4*)(sH + r*HSTR + c) = o4;
            }
        }
    }
    __syncthreads();

    // ========== attention: register accumulator = attn@wo + bo ==========
    // layout: acc[rr][jt][p] covers row 4w+rr, cols jt*128 + 4l + {2p, 2p+1}
    u64 acc[4][3][2];
    #pragma unroll
    for (int jt = 0; jt < 3; jt++) {
        float4 bv4 = *(const float4*)(bo + jt*128 + 4*l);
        u64 p0 = pack2(bv4.x, bv4.y), p1 = pack2(bv4.z, bv4.w);
        #pragma unroll
        for (int rr = 0; rr < 4; rr++) { acc[rr][jt][0] = p0; acc[rr][jt][1] = p1; }
    }

    const float kScale = 0.14433756729740643f; // 48^-0.5

    for (int h = 0; h < NH; h++) {
        // ---- q,k,v generation: thread (t0, e6..e6+5) for each matrix ----
        u64 qa[3], ka[3], va[3];
        #pragma unroll
        for (int p = 0; p < 3; p++) {
            qa[p] = pack2(bq [h*HS + e6 + 2*p], bq [h*HS + e6 + 2*p + 1]);
            ka[p] = pack2(bk [h*HS + e6 + 2*p], bk [h*HS + e6 + 2*p + 1]);
            va[p] = pack2(bvv[h*HS + e6 + 2*p], bvv[h*HS + e6 + 2*p + 1]);
        }
        for (int c0 = 0; c0 < DD; c0 += CHUNK_D) {
            __syncthreads();
            // stage wq/wk/wv chunk [CHUNK_D x 48 each] into sW (144 floats per d)
            {
                const int nf4 = CHUNK_D * 144 / 4; // 2304
                for (int i = tid; i < nf4; i += NTHR) {
                    const int dl  = i / 36;
                    const int rem = i - dl*36;
                    const int m   = rem / 12;
                    const int e4  = rem - m*12;
                    const float* src = (m == 0) ? wq : ((m == 1) ? wk : wv);
                    float4 v = *(const float4*)(src + ((size_t)(h*DD + c0 + dl))*HS + e4*4);
                    *(float4*)(sW + dl*144 + m*48 + e4*4) = v;
                }
            }
            __syncthreads();
            #pragma unroll 4
            for (int dl = 0; dl < CHUNK_D; dl++) {
                const u64 hv = bc2(sH[t0*HSTR + c0 + dl]);
                const float* wrow = sW + dl*144 + e6;
                #pragma unroll
                for (int p = 0; p < 3; p++) {
                    qa[p] = fma2(hv, *(const u64*)(wrow +       2*p), qa[p]);
                    ka[p] = fma2(hv, *(const u64*)(wrow + 48  + 2*p), ka[p]);
                    va[p] = fma2(hv, *(const u64*)(wrow + 96  + 2*p), va[p]);
                }
            }
        }
        // write q,k,v to padded smem
        #pragma unroll
        for (int p = 0; p < 3; p++) {
            float2 f;
            f = unp2(qa[p]); sQ[t0*QSTR + e6 + 2*p] = f.x; sQ[t0*QSTR + e6 + 2*p + 1] = f.y;
            f = unp2(ka[p]); sK[t0*QSTR + e6 + 2*p] = f.x; sK[t0*QSTR + e6 + 2*p + 1] = f.y;
            f = unp2(va[p]); sV[t0*QSTR + e6 + 2*p] = f.x; sV[t0*QSTR + e6 + 2*p + 1] = f.y;
        }
        __syncthreads();

        // ---- scores + causal softmax: thread (t0) owns cols s = g + 8k ----
        float sc[8];
        float mx = -1e30f;
        #pragma unroll
        for (int kk = 0; kk < 8; kk++) {
            const int s = g + 8*kk;
            float val = -1e30f;
            if (s <= t0) {
                u64 a = 0ull;
                const float* qrow = sQ + t0*QSTR;
                const float* krow = sK + s*QSTR;
                #pragma unroll
                for (int i = 0; i < 24; i++)
                    a = fma2(*(const u64*)(qrow + 2*i), *(const u64*)(krow + 2*i), a);
                float2 f = unp2(a);
                val = (f.x + f.y) * kScale;
                mx = fmaxf(mx, val);
            }
            sc[kk] = val;
        }
        sRed[t0*16 + g] = mx;
        __syncthreads();
        float rmx = sRed[t0*16];
        #pragma unroll
        for (int i = 1; i < 8; i++) rmx = fmaxf(rmx, sRed[t0*16 + i]);
        float lsum = 0.f;
        #pragma unroll
        for (int kk = 0; kk < 8; kk++) {
            const int s = g + 8*kk;
            const float e = (s <= t0) ? __expf(sc[kk] - rmx) : 0.f;
            sc[kk] = e;
            lsum += e;
        }
        sRed[t0*16 + 8 + g] = lsum;
        __syncthreads();
        float rsum = 0.f;
        #pragma unroll
        for (int i = 0; i < 8; i++) rsum += sRed[t0*16 + 8 + i];
        const float inv = 1.0f / rsum;
        #pragma unroll
        for (int kk = 0; kk < 8; kk++) sS[t0*SSTR + g + 8*kk] = sc[kk] * inv;
        __syncthreads();

        // ---- attnout[t0][e6..e6+5] = probs @ v ----
        u64 oa[3] = {0ull, 0ull, 0ull};
        for (int s = 0; s < TT; s++) {
            const u64 p = bc2(sS[t0*SSTR + s]);
            const float* vrow = sV + s*QSTR + e6;
            #pragma unroll
            for (int i = 0; i < 3; i++)
                oa[i] = fma2(p, *(const u64*)(vrow + 2*i), oa[i]);
        }
        #pragma unroll
        for (int p = 0; p < 3; p++) {
            float2 f = unp2(oa[p]);
            sQ[t0*QSTR + e6 + 2*p] = f.x;   // overwrite q (done with it)
            sQ[t0*QSTR + e6 + 2*p + 1] = f.y;
        }
        __syncthreads();

        // ---- wo projection accumulate (warp layout, 4-row weight reuse) ----
        {
            const float* wobase = wo + (size_t)(h*HS)*DD + 4*l;
            #pragma unroll 2
            for (int c = 0; c < HS; c++) {
                u64 av[4];
                #pragma unroll
                for (int rr = 0; rr < 4; rr++) av[rr] = bc2(sQ[(4*w+rr)*QSTR + c]);
                const float* wrow = wobase + (size_t)c*DD;
                #pragma unroll
                for (int jt = 0; jt < 3; jt++) {
                    float4 wv4 = *(const float4*)(wrow + jt*128);
                    u64 wp0 = pack2(wv4.x, wv4.y), wp1 = pack2(wv4.z, wv4.w);
                    #pragma unroll
                    for (int rr = 0; rr < 4; rr++) {
                        acc[rr][jt][0] = fma2(av[rr], wp0, acc[rr][jt][0]);
                        acc[rr][jt][1] = fma2(av[rr], wp1, acc[rr][jt][1]);
                    }
                }
            }
        }
    } // heads

    // ========== residual + LN2, re-init acc = h2 + b2 ==========
    __syncthreads();
    {
        #pragma unroll
        for (int rr = 0; rr < 4; rr++) {
            const int r = 4*w + rr;
            float hv[12];
            float s1 = 0.f, s2 = 0.f;
            #pragma unroll
            for (int jt = 0; jt < 3; jt++) {
                const int c = jt*128 + 4*l;
                float2 a0 = unp2(acc[rr][jt][0]);
                float2 a1 = unp2(acc[rr][jt][1]);
                hv[4*jt+0] = sH[r*HSTR + c + 0] + a0.x;
                hv[4*jt+1] = sH[r*HSTR + c + 1] + a0.y;
                hv[4*jt+2] = sH[r*HSTR + c + 2] + a1.x;
                hv[4*jt+3] = sH[r*HSTR + c + 3] + a1.y;
            }
            #pragma unroll
            for (int i = 0; i < 12; i++) { s1 += hv[i]; s2 += hv[i]*hv[i]; }
            #pragma unroll
            for (int o = 16; o > 0; o >>= 1) {
                s1 += __shfl_xor_sync(0xffffffffu, s1, o);
                s2 += __shfl_xor_sync(0xffffffffu, s2, o);
            }
            const float mean = s1 * (1.0f/384.0f);
            const float var  = s2 * (1.0f/384.0f) - mean*mean;
            const float rstd = rsqrtf(var + 1e-5f);
            #pragma unroll
            for (int jt = 0; jt < 3; jt++) {
                const int c = jt*128 + 4*l;
                float4 gg  = *(const float4*)(g2 + c);
                float4 bb  = *(const float4*)(be2 + c);
                float4 b2v = *(const float4*)(b2 + c);
                float h0 = (hv[4*jt+0]-mean)*rstd*gg.x + bb.x;
                float h1 = (hv[4*jt+1]-mean)*rstd*gg.y + bb.y;
                float h2 = (hv[4*jt+2]-mean)*rstd*gg.z + bb.z;
                float h3 = (hv[4*jt+3]-mean)*rstd*gg.w + bb.w;
                *(float4*)(sH + r*HSTR + c) = make_float4(h0, h1, h2, h3);
                acc[rr][jt][0] = pack2(h0 + b2v.x, h1 + b2v.y);
                acc[rr][jt][1] = pack2(h2 + b2v.z, h3 + b2v.w);
            }
        }
    }
    __syncthreads();

    // ========== FF: out = h2 + relu(h2@w1 + b1)@w2 + b2 (12 chunks of 128) ==========
    for (int ch = 0; ch < 12; ch++) {
        // FF-a: r = relu(h2 @ w1[:, ch*128 + 4l..] + b1)
        u64 fa[4][2];
        {
            float4 b1v = *(const float4*)(b1 + ch*128 + 4*l);
            u64 p0 = pack2(b1v.x, b1v.y), p1 = pack2(b1v.z, b1v.w);
            #pragma unroll
            for (int rr = 0; rr < 4; rr++) { fa[rr][0] = p0; fa[rr][1] = p1; }
        }
        {
            const float* w1p = w1 + ch*128 + 4*l;
            #pragma unroll 2
            for (int d = 0; d < DD; d += 2) {
                float4 wa = *(const float4*)(w1p + (size_t)d*FFDIM);
                float4 wb = *(const float4*)(w1p + (size_t)(d+1)*FFDIM);
                u64 wa0 = pack2(wa.x, wa.y), wa1 = pack2(wa.z, wa.w);
                u64 wb0 = pack2(wb.x, wb.y), wb1 = pack2(wb.z, wb.w);
                #pragma unroll
                for (int rr = 0; rr < 4; rr++) {
                    float2 hp = *(const float2*)(sH + (4*w+rr)*HSTR + d);
                    u64 h0 = bc2(hp.x), h1 = bc2(hp.y);
                    fa[rr][0] = fma2(h0, wa0, fa[rr][0]);
                    fa[rr][1] = fma2(h0, wa1, fa[rr][1]);
                    fa[rr][0] = fma2(h1, wb0, fa[rr][0]);
                    fa[rr][1] = fma2(h1, wb1, fa[rr][1]);
                }
            }
        }
        #pragma unroll
        for (int rr = 0; rr < 4; rr++) {
            float2 f0 = unp2(fa[rr][0]), f1 = unp2(fa[rr][1]);
            *(float4*)(sR + (4*w+rr)*RSTR + 4*l) =
                make_float4(fmaxf(f0.x, 0.f), fmaxf(f0.y, 0.f),
                            fmaxf(f1.x, 0.f), fmaxf(f1.y, 0.f));
        }
        __syncthreads();

        // FF-b: acc += r @ w2[ch*128.., :]
        {
            const float* w2p = w2 + (size_t)(ch*128)*DD + 4*l;
            #pragma unroll 2
            for (int c = 0; c < 128; c++) {
                u64 rv[4];
                #pragma unroll
                for (int rr = 0; rr < 4; rr++) rv[rr] = bc2(sR[(4*w+rr)*RSTR + c]);
                const float* wrow = w2p + (size_t)c*DD;
                #pragma unroll
                for (int jt = 0; jt < 3; jt++) {
                    float4 wv4 = *(const float4*)(wrow + jt*128);
                    u64 wp0 = pack2(wv4.x, wv4.y), wp1 = pack2(wv4.z, wv4.w);
                    #pragma unroll
                    for (int rr = 0; rr < 4; rr++) {
                        acc[rr][jt][0] = fma2(rv[rr], wp0, acc[rr][jt][0]);
                        acc[rr][jt][1] = fma2(rv[rr], wp1, acc[rr][jt][1]);
                    }
                }
            }
        }
        __syncthreads();
    }

    // ========== store output ==========
    {
        float* ob = out + (size_t)b * TT * DD;
        #pragma unroll
        for (int rr = 0; rr < 4; rr++) {
            const int r = 4*w + rr;
            #pragma unroll
            for (int jt = 0; jt < 3; jt++) {
                float2 a0 = unp2(acc[rr][jt][0]);
                float2 a1 = unp2(acc[rr][jt][1]);
                *(float4*)(ob + r*DD + jt*128 + 4*l) = make_float4(a0.x, a0.y, a1.x, a1.y);
            }
        }
    }
}

extern "C" void kernel_launch(void* const* d_in, const int* in_sizes, int n_in,
                              void* d_out, int out_size) {
    const float* x   = (const float*)d_in[0];
    const float* wq  = (const float*)d_in[1];
    const float* bq  = (const float*)d_in[2];
    const float* wk  = (const float*)d_in[3];
    const float* bk  = (const float*)d_in[4];
    const float* wv  = (const float*)d_in[5];
    const float* bv  = (const float*)d_in[6];
    const float* wo  = (const float*)d_in[7];
    const float* bo  = (const float*)d_in[8];
    const float* w1  = (const float*)d_in[9];
    const float* b1  = (const float*)d_in[10];
    const float* w2  = (const float*)d_in[11];
    const float* b2  = (const float*)d_in[12];
    const float* g1  = (const float*)d_in[13];
    const float* be1 = (const float*)d_in[14];
    const float* g2  = (const float*)d_in[15];
    const float* be2 = (const float*)d_in[16];
    float* out = (float*)d_out;

    const int nb = in_sizes[0] / (TT * DD);
    const size_t smem = (size_t)SMEM_FLOATS * sizeof(float);

    cudaFuncSetAttribute(block_kernel, cudaFuncAttributeMaxDynamicSharedMemorySize, (int)smem);
    block_kernel<<<nb, NTHR, smem>>>(x, wq, bq, wk, bk, wv, bv, wo, bo,
                                     w1, b1, w2, b2, g1, be1, g2, be2, out);
}

// round 7
// speedup vs baseline: 3.1459x; 3.1425x over previous
#include <cuda_runtime.h>
#include <cuda_bf16.h>
#include <cstdint>

#define TT 64
#define DD 384
#define NH 8
#define HS 48
#define FFD 1536
#define NQKV 1152
#define NBMAX 2048
#define MROWS (NBMAX*TT)

typedef unsigned long long u64;
typedef unsigned int u32;

// ======================= device scratch buffers =======================
__device__ __nv_bfloat16 g_wqkv_h[NQKV*DD], g_wqkv_l[NQKV*DD];
__device__ __nv_bfloat16 g_wot_h[DD*DD],  g_wot_l[DD*DD];
__device__ __nv_bfloat16 g_w1t_h[FFD*DD], g_w1t_l[FFD*DD];
__device__ __nv_bfloat16 g_w2t_h[DD*FFD], g_w2t_l[DD*FFD];
__device__ float g_bqkv[NQKV];
__device__ float g_h[(size_t)MROWS*DD];
__device__ __nv_bfloat16 g_h_hi[(size_t)MROWS*DD], g_h_lo[(size_t)MROWS*DD];
__device__ float g_qkv[(size_t)MROWS*NQKV];
__device__ __nv_bfloat16 g_at_hi[(size_t)MROWS*DD], g_at_lo[(size_t)MROWS*DD];
__device__ float g_s[(size_t)MROWS*DD];
__device__ float g_h2[(size_t)MROWS*DD];
__device__ __nv_bfloat16 g_h2_hi[(size_t)MROWS*DD], g_h2_lo[(size_t)MROWS*DD];
__device__ __nv_bfloat16 g_r_hi[(size_t)MROWS*FFD], g_r_lo[(size_t)MROWS*FFD];

// ======================= helpers =======================
__device__ __forceinline__ u64 pack2(float lo, float hi) {
    u64 r; asm("mov.b64 %0, {%1, %2};" : "=l"(r) : "f"(lo), "f"(hi)); return r;
}
__device__ __forceinline__ u64 bc2(float v) { return pack2(v, v); }
__device__ __forceinline__ float2 unp2(u64 v) {
    float2 f; asm("mov.b64 {%0, %1}, %2;" : "=f"(f.x), "=f"(f.y) : "l"(v)); return f;
}
__device__ __forceinline__ u64 fma2(u64 a, u64 b, u64 c) {
    u64 d; asm("fma.rn.f32x2 %0, %1, %2, %3;" : "=l"(d) : "l"(a), "l"(b), "l"(c)); return d;
}
__device__ __forceinline__ void split2(float x, __nv_bfloat16& hi, __nv_bfloat16& lo) {
    hi = __float2bfloat16(x);
    lo = __float2bfloat16(x - __bfloat162float(hi));
}
__device__ __forceinline__ u32 smem_u32(const void* p) {
    u32 a; asm("{ .reg .u64 t; cvta.to.shared.u64 t, %1; cvt.u32.u64 %0, t; }" : "=r"(a) : "l"(p));
    return a;
}
__device__ __forceinline__ void cp16(u32 dst, const void* src) {
    asm volatile("cp.async.cg.shared.global [%0], [%1], 16;" :: "r"(dst), "l"(src));
}
#define CP_COMMIT()  asm volatile("cp.async.commit_group;" ::: "memory")
#define CP_WAIT(n)   asm volatile("cp.async.wait_group %0;" :: "n"(n) : "memory")

__device__ __forceinline__ void ldsm_x4(u32 addr, u32* r) {
    asm volatile("ldmatrix.sync.aligned.m8n8.x4.shared.b16 {%0,%1,%2,%3}, [%4];"
        : "=r"(r[0]), "=r"(r[1]), "=r"(r[2]), "=r"(r[3]) : "r"(addr));
}
__device__ __forceinline__ void mma_bf16(float* c, const u32* a, const u32* b) {
    asm volatile("mma.sync.aligned.m16n8k16.row.col.f32.bf16.bf16.f32 "
        "{%0,%1,%2,%3}, {%4,%5,%6,%7}, {%8,%9}, {%0,%1,%2,%3};"
        : "+f"(c[0]), "+f"(c[1]), "+f"(c[2]), "+f"(c[3])
        : "r"(a[0]), "r"(a[1]), "r"(a[2]), "r"(a[3]), "r"(b[0]), "r"(b[1]));
}

// ======================= weight split / transpose =======================
__global__ void split_weights_kernel(
    const float* __restrict__ wq, const float* __restrict__ bq,
    const float* __restrict__ wk, const float* __restrict__ bk,
    const float* __restrict__ wv, const float* __restrict__ bv,
    const float* __restrict__ wo, const float* __restrict__ w1,
    const float* __restrict__ w2)
{
    const int stride = gridDim.x * blockDim.x;
    const int t0 = blockIdx.x * blockDim.x + threadIdx.x;
    for (int i = t0; i < NQKV*DD; i += stride) {
        int n = i / DD, k = i - n*DD;
        int h = n / 144, rm = n - h*144, m = rm / 48, e = rm - m*48;
        const float* src = (m==0) ? wq : ((m==1) ? wk : wv);
        split2(src[((size_t)(h*DD + k))*HS + e], g_wqkv_h[i], g_wqkv_l[i]);
    }
    for (int i = t0; i < DD*DD; i += stride) {
        int n = i / DD, k = i - n*DD;
        split2(wo[(size_t)k*DD + n], g_wot_h[i], g_wot_l[i]);
    }
    for (int i = t0; i < FFD*DD; i += stride) {
        int n = i / DD, k = i - n*DD;
        split2(w1[(size_t)k*FFD + n], g_w1t_h[i], g_w1t_l[i]);
    }
    for (int i = t0; i < DD*FFD; i += stride) {
        int n = i / FFD, k = i - n*FFD;
        split2(w2[(size_t)k*DD + n], g_w2t_h[i], g_w2t_l[i]);
    }
    for (int i = t0; i < NQKV; i += stride) {
        int h = i / 144, rm = i - h*144, m = rm / 48, e = rm - m*48;
        g_bqkv[i] = (m==0 ? bq : (m==1 ? bk : bv))[h*HS + e];
    }
}

// ======================= layernorm (+optional add) + bf16 split =======================
__global__ __launch_bounds__(256) void ln_kernel(
    const float* __restrict__ in1, const float* __restrict__ in2,
    const float* __restrict__ gg, const float* __restrict__ bb,
    float* __restrict__ outf, __nv_bfloat16* __restrict__ oh, __nv_bfloat16* __restrict__ ol,
    int nrows)
{
    int r = blockIdx.x*8 + (threadIdx.x >> 5);
    int l = threadIdx.x & 31;
    if (r >= nrows) return;
    size_t ro = (size_t)r * DD;
    float v[12]; float s1 = 0.f, s2 = 0.f;
    #pragma unroll
    for (int jt = 0; jt < 3; jt++) {
        int c = jt*128 + 4*l;
        float4 a = *(const float4*)(in1 + ro + c);
        if (in2) {
            float4 b = *(const float4*)(in2 + ro + c);
            a.x += b.x; a.y += b.y; a.z += b.z; a.w += b.w;
        }
        v[4*jt+0]=a.x; v[4*jt+1]=a.y; v[4*jt+2]=a.z; v[4*jt+3]=a.w;
    }
    #pragma unroll
    for (int i = 0; i < 12; i++) { s1 += v[i]; s2 += v[i]*v[i]; }
    #pragma unroll
    for (int o = 16; o > 0; o >>= 1) {
        s1 += __shfl_xor_sync(0xffffffffu, s1, o);
        s2 += __shfl_xor_sync(0xffffffffu, s2, o);
    }
    float mean = s1 * (1.0f/384.0f);
    float var  = s2 * (1.0f/384.0f) - mean*mean;
    float rstd = rsqrtf(var + 1e-5f);
    #pragma unroll
    for (int jt = 0; jt < 3; jt++) {
        int c = jt*128 + 4*l;
        float4 gv = *(const float4*)(gg + c);
        float4 bv = *(const float4*)(bb + c);
        float y0 = (v[4*jt+0]-mean)*rstd*gv.x + bv.x;
        float y1 = (v[4*jt+1]-mean)*rstd*gv.y + bv.y;
        float y2 = (v[4*jt+2]-mean)*rstd*gv.z + bv.z;
        float y3 = (v[4*jt+3]-mean)*rstd*gv.w + bv.w;
        *(float4*)(outf + ro + c) = make_float4(y0, y1, y2, y3);
        __nv_bfloat16 h0,l0,h1,l1,h2,l2,h3,l3;
        split2(y0,h0,l0); split2(y1,h1,l1); split2(y2,h2,l2); split2(y3,h3,l3);
        __nv_bfloat162 p;
        p.x=h0; p.y=h1; *(__nv_bfloat162*)(oh + ro + c)     = p;
        p.x=h2; p.y=h3; *(__nv_bfloat162*)(oh + ro + c + 2) = p;
        p.x=l0; p.y=l1; *(__nv_bfloat162*)(ol + ro + c)     = p;
        p.x=l2; p.y=l3; *(__nv_bfloat162*)(ol + ro + c + 2) = p;
    }
}

// ======================= split GEMM via mma.sync (HMMA bf16) =======================
// D[128x128] tile of A[M,K] @ B[Ntot,K]^T ; A,B bf16 hi/lo split.
// mode 0: outf = D + bias
// mode 2: (oh,ol) = split(relu(D + bias))
// mode 3: outf = D + bias + resid
// smem per stage: 4 arrays (Ah, Al, Bh, Bl), each 128 rows x 64 cols bf16,
// row stride 72 bf16 (144 B) -> conflict-free ldmatrix. 18432 B per array.
#define ARR_BYTES 18432
#define STG_BYTES (4*ARR_BYTES)          // 73728
#define GSM_TOTAL (2*STG_BYTES)          // 147456

__global__ __launch_bounds__(256, 1) void gemm_kernel(
    const __nv_bfloat16* __restrict__ Ah, const __nv_bfloat16* __restrict__ Al,
    const __nv_bfloat16* __restrict__ Bh, const __nv_bfloat16* __restrict__ Bl,
    const float* __restrict__ bias, const float* __restrict__ resid,
    float* __restrict__ outf, __nv_bfloat16* __restrict__ oh, __nv_bfloat16* __restrict__ ol,
    int K, int Ntiles, int Ntot, int mode)
{
    extern __shared__ char smem[];
    const u32 smem_base = smem_u32(smem);
    const int tid = threadIdx.x;
    const int wid = tid >> 5;
    const int lane = tid & 31;

    const int mt = blockIdx.x / Ntiles;
    const int nt = blockIdx.x - mt * Ntiles;
    const size_t arow = (size_t)mt * 128;
    const size_t brow = (size_t)nt * 128;

    const __nv_bfloat16* Abase_h = Ah + arow * (size_t)K;
    const __nv_bfloat16* Abase_l = Al + arow * (size_t)K;
    const __nv_bfloat16* Bbase_h = Bh + brow * (size_t)K;
    const __nv_bfloat16* Bbase_l = Bl + brow * (size_t)K;

    const int wm = wid & 1;    // 2 m-blocks of 64
    const int wn = wid >> 1;   // 4 n-blocks of 32

    // ldmatrix per-thread address components (bytes)
    const u32 a_off = (u32)(((wm*64 + (lane & 15)) * 72 + ((lane >> 4) * 8)) * 2);
    const u32 b_off = (u32)(((wn*32 + ((lane & 7) | ((lane >> 1) & 8))) * 72
                             + (((lane >> 3) & 1) * 8)) * 2);

    float c[4][4][4];
    #pragma unroll
    for (int mi = 0; mi < 4; mi++)
        #pragma unroll
        for (int ni = 0; ni < 4; ni++)
            #pragma unroll
            for (int j = 0; j < 4; j++) c[mi][ni][j] = 0.f;

    const int nc = K >> 6;

    auto load_chunk = [&](int stage, int cc) {
        const u32 sb = smem_base + stage * STG_BYTES;
        const int c0 = cc << 6;
        #pragma unroll
        for (int i = 0; i < 16; i++) {
            int s = tid + (i << 8);
            int arr = s >> 10;             // 0..3, constant per i
            int within = s & 1023;
            int r   = within >> 3;
            int c16 = within & 7;
            const __nv_bfloat16* bp = (arr == 0) ? Abase_h : (arr == 1) ? Abase_l
                                     : (arr == 2) ? Bbase_h : Bbase_l;
            const void* src = bp + (size_t)r * K + c0 + (c16 << 3);
            u32 dst = sb + arr * ARR_BYTES + (u32)(r * 144 + (c16 << 4));
            cp16(dst, src);
        }
        CP_COMMIT();
    };

    load_chunk(0, 0);
    for (int cc = 0; cc < nc; cc++) {
        const int cur = cc & 1;
        if (cc + 1 < nc) { load_chunk((cc + 1) & 1, cc + 1); CP_WAIT(1); }
        else             { CP_WAIT(0); }
        __syncthreads();

        const u32 sb = smem_base + cur * STG_BYTES;
        const u32 sa_h = sb + a_off;
        const u32 sa_l = sb + ARR_BYTES   + a_off;
        const u32 sb_h = sb + 2*ARR_BYTES + b_off;
        const u32 sb_l = sb + 3*ARR_BYTES + b_off;

        #pragma unroll
        for (int ks = 0; ks < 4; ks++) {
            const u32 ko = (u32)(ks * 32);     // ks*16 cols * 2B
            u32 ah[4][4], al[4][4], bb[2][4];
            #pragma unroll
            for (int mi = 0; mi < 4; mi++) {
                ldsm_x4(sa_h + (u32)(mi * 2304) + ko, ah[mi]);
                ldsm_x4(sa_l + (u32)(mi * 2304) + ko, al[mi]);
            }
            #pragma unroll
            for (int nb = 0; nb < 2; nb++)
                ldsm_x4(sb_h + (u32)(nb * 2304) + ko, bb[nb]);
            // hi*hi and lo*hi
            #pragma unroll
            for (int mi = 0; mi < 4; mi++)
                #pragma unroll
                for (int ni = 0; ni < 4; ni++) {
                    mma_bf16(c[mi][ni], ah[mi], &bb[ni >> 1][(ni & 1) * 2]);
                    mma_bf16(c[mi][ni], al[mi], &bb[ni >> 1][(ni & 1) * 2]);
                }
            // hi*lo
            #pragma unroll
            for (int nb = 0; nb < 2; nb++)
                ldsm_x4(sb_l + (u32)(nb * 2304) + ko, bb[nb]);
            #pragma unroll
            for (int mi = 0; mi < 4; mi++)
                #pragma unroll
                for (int ni = 0; ni < 4; ni++)
                    mma_bf16(c[mi][ni], ah[mi], &bb[ni >> 1][(ni & 1) * 2]);
        }
        __syncthreads();
    }

    // ---- epilogue: c[mi][ni] covers rows wm*64+mi*16+(lane>>2)+{0,8},
    //                cols wn*32+ni*8+(lane&3)*2 ----
    const int r0 = wm*64 + (lane >> 2);
    const int cc0 = wn*32 + (lane & 3)*2;

    #pragma unroll
    for (int mi = 0; mi < 4; mi++) {
        #pragma unroll
        for (int half = 0; half < 2; half++) {
            const size_t orow = arow + r0 + mi*16 + half*8;
            #pragma unroll
            for (int ni = 0; ni < 4; ni++) {
                const size_t ncol = brow + cc0 + ni*8;
                float v0 = c[mi][ni][half*2+0] + bias[ncol];
                float v1 = c[mi][ni][half*2+1] + bias[ncol+1];
                if (mode == 2) {
                    v0 = fmaxf(v0, 0.f); v1 = fmaxf(v1, 0.f);
                    __nv_bfloat16 h0,l0,h1,l1;
                    split2(v0,h0,l0); split2(v1,h1,l1);
                    __nv_bfloat162 p;
                    p.x=h0; p.y=h1; *(__nv_bfloat162*)(oh + orow*(size_t)Ntot + ncol) = p;
                    p.x=l0; p.y=l1; *(__nv_bfloat162*)(ol + orow*(size_t)Ntot + ncol) = p;
                } else if (mode == 3) {
                    const float* rp = resid + orow*(size_t)Ntot + ncol;
                    float2 o; o.x = v0 + rp[0]; o.y = v1 + rp[1];
                    *(float2*)(outf + orow*(size_t)Ntot + ncol) = o;
                } else {
                    float2 o; o.x = v0; o.y = v1;
                    *(float2*)(outf + orow*(size_t)Ntot + ncol) = o;
                }
            }
        }
    }
}

// ======================= attention core (fp32) =======================
#define AQ_STR 52
#define AS_STR 68
#define ASM_FLOATS ((3*AQ_STR + AS_STR + 16) * TT)

__global__ __launch_bounds__(512) void attn_kernel(int nb)
{
    extern __shared__ float sma[];
    float* sQ   = sma;
    float* sK   = sQ + TT*AQ_STR;
    float* sV   = sK + TT*AQ_STR;
    float* sS   = sV + TT*AQ_STR;
    float* sRed = sS + TT*AS_STR;

    const int tid = threadIdx.x;
    const int b   = blockIdx.x;
    const int t0  = tid >> 3;
    const int g   = tid & 7;
    const int e6  = g * 6;
    const float kScale = 0.14433756729740643f;   // 48^-0.5
    const size_t rowbase = (size_t)(b*TT + t0);

    for (int h = 0; h < NH; h++) {
        __syncthreads();
        {
            const float* src = g_qkv + rowbase * NQKV + h*144 + e6;
            #pragma unroll
            for (int p = 0; p < 3; p++) {
                float2 q2 = *(const float2*)(src +       2*p);
                float2 k2 = *(const float2*)(src + 48  + 2*p);
                float2 v2 = *(const float2*)(src + 96  + 2*p);
                sQ[t0*AQ_STR + e6 + 2*p] = q2.x; sQ[t0*AQ_STR + e6 + 2*p + 1] = q2.y;
                sK[t0*AQ_STR + e6 + 2*p] = k2.x; sK[t0*AQ_STR + e6 + 2*p + 1] = k2.y;
                sV[t0*AQ_STR + e6 + 2*p] = v2.x; sV[t0*AQ_STR + e6 + 2*p + 1] = v2.y;
            }
        }
        __syncthreads();

        float sc[8];
        float mx = -1e30f;
        #pragma unroll
        for (int kk = 0; kk < 8; kk++) {
            const int s = g + 8*kk;
            float val = -1e30f;
            if (s <= t0) {
                u64 a = 0ull;
                const float* qrow = sQ + t0*AQ_STR;
                const float* krow = sK + s*AQ_STR;
                #pragma unroll
                for (int i = 0; i < 24; i++)
                    a = fma2(*(const u64*)(qrow + 2*i), *(const u64*)(krow + 2*i), a);
                float2 f = unp2(a);
                val = (f.x + f.y) * kScale;
                mx = fmaxf(mx, val);
            }
            sc[kk] = val;
        }
        sRed[t0*16 + g] = mx;
        __syncthreads();
        float rmx = sRed[t0*16];
        #pragma unroll
        for (int i = 1; i < 8; i++) rmx = fmaxf(rmx, sRed[t0*16 + i]);
        float lsum = 0.f;
        #pragma unroll
        for (int kk = 0; kk < 8; kk++) {
            const int s = g + 8*kk;
            const float e = (s <= t0) ? __expf(sc[kk] - rmx) : 0.f;
            sc[kk] = e;
            lsum += e;
        }
        sRed[t0*16 + 8 + g] = lsum;
        __syncthreads();
        float rsum = 0.f;
        #pragma unroll
        for (int i = 0; i < 8; i++) rsum += sRed[t0*16 + 8 + i];
        const float inv = 1.0f / rsum;
        #pragma unroll
        for (int kk = 0; kk < 8; kk++) sS[t0*AS_STR + g + 8*kk] = sc[kk] * inv;
        __syncthreads();

        u64 oa[3] = {0ull, 0ull, 0ull};
        for (int s = 0; s < TT; s++) {
            const u64 p = bc2(sS[t0*AS_STR + s]);
            const float* vrow = sV + s*AQ_STR + e6;
            #pragma unroll
            for (int i = 0; i < 3; i++)
                oa[i] = fma2(p, *(const u64*)(vrow + 2*i), oa[i]);
        }
        {
            __nv_bfloat16* dh = g_at_hi + rowbase * DD + h*HS + e6;
            __nv_bfloat16* dl = g_at_lo + rowbase * DD + h*HS + e6;
            #pragma unroll
            for (int p = 0; p < 3; p++) {
                float2 f = unp2(oa[p]);
                __nv_bfloat16 h0,l0,h1,l1;
                split2(f.x,h0,l0); split2(f.y,h1,l1);
                __nv_bfloat162 ph; ph.x=h0; ph.y=h1;
                __nv_bfloat162 pl; pl.x=l0; pl.y=l1;
                *(__nv_bfloat162*)(dh + 2*p) = ph;
                *(__nv_bfloat162*)(dl + 2*p) = pl;
            }
        }
    }
}

// ======================= host launcher =======================
template <typename T>
static void* sym_addr(T& sym) { void* p = nullptr; cudaGetSymbolAddress(&p, sym); return p; }

extern "C" void kernel_launch(void* const* d_in, const int* in_sizes, int n_in,
                              void* d_out, int out_size) {
    const float* x   = (const float*)d_in[0];
    const float* wq  = (const float*)d_in[1];
    const float* bq  = (const float*)d_in[2];
    const float* wk  = (const float*)d_in[3];
    const float* bk  = (const float*)d_in[4];
    const float* wv  = (const float*)d_in[5];
    const float* bv  = (const float*)d_in[6];
    const float* wo  = (const float*)d_in[7];
    const float* bo  = (const float*)d_in[8];
    const float* w1  = (const float*)d_in[9];
    const float* b1  = (const float*)d_in[10];
    const float* w2  = (const float*)d_in[11];
    const float* b2  = (const float*)d_in[12];
    const float* g1  = (const float*)d_in[13];
    const float* be1 = (const float*)d_in[14];
    const float* g2  = (const float*)d_in[15];
    const float* be2 = (const float*)d_in[16];
    float* out = (float*)d_out;

    const int nb = in_sizes[0] / (TT * DD);
    const int M  = nb * TT;
    const int Mtiles = M / 128;

    float* p_h      = (float*)sym_addr(g_h);
    __nv_bfloat16* p_h_hi = (__nv_bfloat16*)sym_addr(g_h_hi);
    __nv_bfloat16* p_h_lo = (__nv_bfloat16*)sym_addr(g_h_lo);
    float* p_qkv    = (float*)sym_addr(g_qkv);
    __nv_bfloat16* p_at_hi = (__nv_bfloat16*)sym_addr(g_at_hi);
    __nv_bfloat16* p_at_lo = (__nv_bfloat16*)sym_addr(g_at_lo);
    float* p_s      = (float*)sym_addr(g_s);
    float* p_h2     = (float*)sym_addr(g_h2);
    __nv_bfloat16* p_h2_hi = (__nv_bfloat16*)sym_addr(g_h2_hi);
    __nv_bfloat16* p_h2_lo = (__nv_bfloat16*)sym_addr(g_h2_lo);
    __nv_bfloat16* p_r_hi  = (__nv_bfloat16*)sym_addr(g_r_hi);
    __nv_bfloat16* p_r_lo  = (__nv_bfloat16*)sym_addr(g_r_lo);
    __nv_bfloat16* p_wqkv_h = (__nv_bfloat16*)sym_addr(g_wqkv_h);
    __nv_bfloat16* p_wqkv_l = (__nv_bfloat16*)sym_addr(g_wqkv_l);
    __nv_bfloat16* p_wot_h  = (__nv_bfloat16*)sym_addr(g_wot_h);
    __nv_bfloat16* p_wot_l  = (__nv_bfloat16*)sym_addr(g_wot_l);
    __nv_bfloat16* p_w1t_h  = (__nv_bfloat16*)sym_addr(g_w1t_h);
    __nv_bfloat16* p_w1t_l  = (__nv_bfloat16*)sym_addr(g_w1t_l);
    __nv_bfloat16* p_w2t_h  = (__nv_bfloat16*)sym_addr(g_w2t_h);
    __nv_bfloat16* p_w2t_l  = (__nv_bfloat16*)sym_addr(g_w2t_l);
    float* p_bqkv   = (float*)sym_addr(g_bqkv);

    cudaFuncSetAttribute(gemm_kernel, cudaFuncAttributeMaxDynamicSharedMemorySize, GSM_TOTAL);
    cudaFuncSetAttribute(attn_kernel, cudaFuncAttributeMaxDynamicSharedMemorySize,
                         (int)(ASM_FLOATS * sizeof(float)));

    // 1. weight split / transpose
    split_weights_kernel<<<1024, 256>>>(wq, bq, wk, bk, wv, bv, wo, w1, w2);

    // 2. LN1: x -> h (float + bf16 split)
    ln_kernel<<<M/8, 256>>>(x, nullptr, g1, be1, p_h, p_h_hi, p_h_lo, M);

    // 3. QKV GEMM: qkv = h @ wqkv^T + bqkv
    gemm_kernel<<<Mtiles*9, 256, GSM_TOTAL>>>(
        p_h_hi, p_h_lo, p_wqkv_h, p_wqkv_l, p_bqkv, nullptr,
        p_qkv, nullptr, nullptr, DD, 9, NQKV, 0);

    // 4. attention core
    attn_kernel<<<nb, 512, ASM_FLOATS * sizeof(float)>>>(nb);

    // 5. wo GEMM: s = at @ wo + bo
    gemm_kernel<<<Mtiles*3, 256, GSM_TOTAL>>>(
        p_at_hi, p_at_lo, p_wot_h, p_wot_l, bo, nullptr,
        p_s, nullptr, nullptr, DD, 3, DD, 0);

    // 6. LN2: h2 = ln(h + s)
    ln_kernel<<<M/8, 256>>>(p_h, p_s, g2, be2, p_h2, p_h2_hi, p_h2_lo, M);

    // 7. FF1: r = relu(h2 @ w1 + b1) (bf16 split out)
    gemm_kernel<<<Mtiles*12, 256, GSM_TOTAL>>>(
        p_h2_hi, p_h2_lo, p_w1t_h, p_w1t_l, b1, nullptr,
        nullptr, p_r_hi, p_r_lo, DD, 12, FFD, 2);

    // 8. FF2: out = r @ w2 + b2 + h2
    gemm_kernel<<<Mtiles*3, 256, GSM_TOTAL>>>(
        p_r_hi, p_r_lo, p_w2t_h, p_w2t_l, b2, p_h2,
        out, nullptr, nullptr, FFD, 3, DD, 3);
}

// round 8
// speedup vs baseline: 3.2910x; 1.0461x over previous
#include <cuda_runtime.h>
#include <cuda_bf16.h>
#include <cstdint>

#define TT 64
#define DD 384
#define NH 8
#define HS 48
#define FFD 1536
#define NQKV 1152
#define NBMAX 2048
#define MROWS (NBMAX*TT)

typedef unsigned long long u64;
typedef unsigned int u32;

// ======================= device scratch buffers =======================
__device__ __nv_bfloat16 g_wqkv_h[NQKV*DD], g_wqkv_l[NQKV*DD];
__device__ __nv_bfloat16 g_wot_h[DD*DD],  g_wot_l[DD*DD];
__device__ __nv_bfloat16 g_w1t_h[FFD*DD], g_w1t_l[FFD*DD];
__device__ __nv_bfloat16 g_w2t_h[DD*FFD], g_w2t_l[DD*FFD];
__device__ float g_bqkv[NQKV];
__device__ float g_h[(size_t)MROWS*DD];
__device__ __nv_bfloat16 g_h_hi[(size_t)MROWS*DD], g_h_lo[(size_t)MROWS*DD];
__device__ float g_qkv[(size_t)MROWS*NQKV];
__device__ __nv_bfloat16 g_at_hi[(size_t)MROWS*DD], g_at_lo[(size_t)MROWS*DD];
__device__ float g_s[(size_t)MROWS*DD];
__device__ float g_h2[(size_t)MROWS*DD];
__device__ __nv_bfloat16 g_h2_hi[(size_t)MROWS*DD], g_h2_lo[(size_t)MROWS*DD];
__device__ __nv_bfloat16 g_r_hi[(size_t)MROWS*FFD], g_r_lo[(size_t)MROWS*FFD];

// ======================= helpers =======================
__device__ __forceinline__ u64 pack2(float lo, float hi) {
    u64 r; asm("mov.b64 %0, {%1, %2};" : "=l"(r) : "f"(lo), "f"(hi)); return r;
}
__device__ __forceinline__ u64 bc2(float v) { return pack2(v, v); }
__device__ __forceinline__ float2 unp2(u64 v) {
    float2 f; asm("mov.b64 {%0, %1}, %2;" : "=f"(f.x), "=f"(f.y) : "l"(v)); return f;
}
__device__ __forceinline__ u64 fma2(u64 a, u64 b, u64 c) {
    u64 d; asm("fma.rn.f32x2 %0, %1, %2, %3;" : "=l"(d) : "l"(a), "l"(b), "l"(c)); return d;
}
__device__ __forceinline__ void split2(float x, __nv_bfloat16& hi, __nv_bfloat16& lo) {
    hi = __float2bfloat16(x);
    lo = __float2bfloat16(x - __bfloat162float(hi));
}
__device__ __forceinline__ u32 smem_u32(const void* p) {
    u32 a; asm("{ .reg .u64 t; cvta.to.shared.u64 t, %1; cvt.u32.u64 %0, t; }" : "=r"(a) : "l"(p));
    return a;
}
__device__ __forceinline__ void cp16(u32 dst, const void* src) {
    asm volatile("cp.async.cg.shared.global [%0], [%1], 16;" :: "r"(dst), "l"(src));
}
#define CP_COMMIT()  asm volatile("cp.async.commit_group;" ::: "memory")
#define CP_WAIT(n)   asm volatile("cp.async.wait_group %0;" :: "n"(n) : "memory")

__device__ __forceinline__ void ldsm_x4(u32 addr, u32* r) {
    asm volatile("ldmatrix.sync.aligned.m8n8.x4.shared.b16 {%0,%1,%2,%3}, [%4];"
        : "=r"(r[0]), "=r"(r[1]), "=r"(r[2]), "=r"(r[3]) : "r"(addr));
}
__device__ __forceinline__ void mma_bf16(float* c, const u32* a, const u32* b) {
    asm volatile("mma.sync.aligned.m16n8k16.row.col.f32.bf16.bf16.f32 "
        "{%0,%1,%2,%3}, {%4,%5,%6,%7}, {%8,%9}, {%0,%1,%2,%3};"
        : "+f"(c[0]), "+f"(c[1]), "+f"(c[2]), "+f"(c[3])
        : "r"(a[0]), "r"(a[1]), "r"(a[2]), "r"(a[3]), "r"(b[0]), "r"(b[1]));
}

// ======================= weight split / transpose =======================
__global__ void split_weights_kernel(
    const float* __restrict__ wq, const float* __restrict__ bq,
    const float* __restrict__ wk, const float* __restrict__ bk,
    const float* __restrict__ wv, const float* __restrict__ bv,
    const float* __restrict__ wo, const float* __restrict__ w1,
    const float* __restrict__ w2)
{
    const int stride = gridDim.x * blockDim.x;
    const int t0 = blockIdx.x * blockDim.x + threadIdx.x;
    for (int i = t0; i < NQKV*DD; i += stride) {
        int n = i / DD, k = i - n*DD;
        int h = n / 144, rm = n - h*144, m = rm / 48, e = rm - m*48;
        const float* src = (m==0) ? wq : ((m==1) ? wk : wv);
        split2(src[((size_t)(h*DD + k))*HS + e], g_wqkv_h[i], g_wqkv_l[i]);
    }
    for (int i = t0; i < DD*DD; i += stride) {
        int n = i / DD, k = i - n*DD;
        split2(wo[(size_t)k*DD + n], g_wot_h[i], g_wot_l[i]);
    }
    for (int i = t0; i < FFD*DD; i += stride) {
        int n = i / DD, k = i - n*DD;
        split2(w1[(size_t)k*FFD + n], g_w1t_h[i], g_w1t_l[i]);
    }
    for (int i = t0; i < DD*FFD; i += stride) {
        int n = i / FFD, k = i - n*FFD;
        split2(w2[(size_t)k*DD + n], g_w2t_h[i], g_w2t_l[i]);
    }
    for (int i = t0; i < NQKV; i += stride) {
        int h = i / 144, rm = i - h*144, m = rm / 48, e = rm - m*48;
        g_bqkv[i] = (m==0 ? bq : (m==1 ? bk : bv))[h*HS + e];
    }
}

// ======================= layernorm (+optional add) + bf16 split =======================
__global__ __launch_bounds__(256) void ln_kernel(
    const float* __restrict__ in1, const float* __restrict__ in2,
    const float* __restrict__ gg, const float* __restrict__ bb,
    float* __restrict__ outf, __nv_bfloat16* __restrict__ oh, __nv_bfloat16* __restrict__ ol,
    int nrows)
{
    int r = blockIdx.x*8 + (threadIdx.x >> 5);
    int l = threadIdx.x & 31;
    if (r >= nrows) return;
    size_t ro = (size_t)r * DD;
    float v[12]; float s1 = 0.f, s2 = 0.f;
    #pragma unroll
    for (int jt = 0; jt < 3; jt++) {
        int c = jt*128 + 4*l;
        float4 a = *(const float4*)(in1 + ro + c);
        if (in2) {
            float4 b = *(const float4*)(in2 + ro + c);
            a.x += b.x; a.y += b.y; a.z += b.z; a.w += b.w;
        }
        v[4*jt+0]=a.x; v[4*jt+1]=a.y; v[4*jt+2]=a.z; v[4*jt+3]=a.w;
    }
    #pragma unroll
    for (int i = 0; i < 12; i++) { s1 += v[i]; s2 += v[i]*v[i]; }
    #pragma unroll
    for (int o = 16; o > 0; o >>= 1) {
        s1 += __shfl_xor_sync(0xffffffffu, s1, o);
        s2 += __shfl_xor_sync(0xffffffffu, s2, o);
    }
    float mean = s1 * (1.0f/384.0f);
    float var  = s2 * (1.0f/384.0f) - mean*mean;
    float rstd = rsqrtf(var + 1e-5f);
    #pragma unroll
    for (int jt = 0; jt < 3; jt++) {
        int c = jt*128 + 4*l;
        float4 gv = *(const float4*)(gg + c);
        float4 bv = *(const float4*)(bb + c);
        float y0 = (v[4*jt+0]-mean)*rstd*gv.x + bv.x;
        float y1 = (v[4*jt+1]-mean)*rstd*gv.y + bv.y;
        float y2 = (v[4*jt+2]-mean)*rstd*gv.z + bv.z;
        float y3 = (v[4*jt+3]-mean)*rstd*gv.w + bv.w;
        *(float4*)(outf + ro + c) = make_float4(y0, y1, y2, y3);
        __nv_bfloat16 h0,l0,h1,l1,h2,l2,h3,l3;
        split2(y0,h0,l0); split2(y1,h1,l1); split2(y2,h2,l2); split2(y3,h3,l3);
        __nv_bfloat162 p;
        p.x=h0; p.y=h1; *(__nv_bfloat162*)(oh + ro + c)     = p;
        p.x=h2; p.y=h3; *(__nv_bfloat162*)(oh + ro + c + 2) = p;
        p.x=l0; p.y=l1; *(__nv_bfloat162*)(ol + ro + c)     = p;
        p.x=l2; p.y=l3; *(__nv_bfloat162*)(ol + ro + c + 2) = p;
    }
}

// ======================= split GEMM via mma.sync (HMMA bf16) =======================
// K-chunk 32, row stride 80B (conflict-free ldmatrix), 2 CTAs/SM.
#define ARR_BYTES 10240                  // 128 rows * 80 B
#define STG_BYTES (4*ARR_BYTES)          // 40960
#define GSM_TOTAL (2*STG_BYTES)          // 81920

__global__ __launch_bounds__(256, 2) void gemm_kernel(
    const __nv_bfloat16* __restrict__ Ah, const __nv_bfloat16* __restrict__ Al,
    const __nv_bfloat16* __restrict__ Bh, const __nv_bfloat16* __restrict__ Bl,
    const float* __restrict__ bias, const float* __restrict__ resid,
    float* __restrict__ outf, __nv_bfloat16* __restrict__ oh, __nv_bfloat16* __restrict__ ol,
    int K, int Ntiles, int Ntot, int mode)
{
    extern __shared__ char smem[];
    const u32 smem_base = smem_u32(smem);
    const int tid = threadIdx.x;
    const int wid = tid >> 5;
    const int lane = tid & 31;

    const int mt = blockIdx.x / Ntiles;
    const int nt = blockIdx.x - mt * Ntiles;
    const size_t arow = (size_t)mt * 128;
    const size_t brow = (size_t)nt * 128;

    const __nv_bfloat16* Abase_h = Ah + arow * (size_t)K;
    const __nv_bfloat16* Abase_l = Al + arow * (size_t)K;
    const __nv_bfloat16* Bbase_h = Bh + brow * (size_t)K;
    const __nv_bfloat16* Bbase_l = Bl + brow * (size_t)K;

    const int wm = wid & 1;    // 2 m-blocks of 64
    const int wn = wid >> 1;   // 4 n-blocks of 32

    const u32 a_off = (u32)((wm*64 + (lane & 15)) * 80 + (lane >> 4) * 16);
    const u32 b_off = (u32)((wn*32 + ((lane & 7) | ((lane >> 1) & 8))) * 80
                            + ((lane >> 3) & 1) * 16);

    float c[4][4][4];
    #pragma unroll
    for (int mi = 0; mi < 4; mi++)
        #pragma unroll
        for (int ni = 0; ni < 4; ni++)
            #pragma unroll
            for (int j = 0; j < 4; j++) c[mi][ni][j] = 0.f;

    const int nc = K >> 5;   // K/32 chunks

    auto load_chunk = [&](int stage, int cc) {
        const u32 sb = smem_base + stage * STG_BYTES;
        const int c0 = cc << 5;
        #pragma unroll
        for (int i = 0; i < 8; i++) {
            int s = tid + (i << 8);
            int arr = s >> 9;              // 0..3 (constant per i pair)
            int within = s & 511;
            int r   = within >> 2;
            int c16 = within & 3;
            const __nv_bfloat16* bp = (arr == 0) ? Abase_h : (arr == 1) ? Abase_l
                                     : (arr == 2) ? Bbase_h : Bbase_l;
            const void* src = bp + (size_t)r * K + c0 + (c16 << 3);
            u32 dst = sb + arr * ARR_BYTES + (u32)(r * 80 + (c16 << 4));
            cp16(dst, src);
        }
        CP_COMMIT();
    };

    load_chunk(0, 0);
    for (int cc = 0; cc < nc; cc++) {
        const int cur = cc & 1;
        if (cc + 1 < nc) { load_chunk((cc + 1) & 1, cc + 1); CP_WAIT(1); }
        else             { CP_WAIT(0); }
        __syncthreads();

        const u32 sb = smem_base + cur * STG_BYTES;
        const u32 sa_h = sb + a_off;
        const u32 sa_l = sb + ARR_BYTES   + a_off;
        const u32 sb_h = sb + 2*ARR_BYTES + b_off;
        const u32 sb_l = sb + 3*ARR_BYTES + b_off;

        #pragma unroll
        for (int ks = 0; ks < 2; ks++) {
            const u32 ko = (u32)(ks * 32);     // 16 cols * 2B
            u32 ah[4][4], al[4][4], bb[2][4];
            #pragma unroll
            for (int mi = 0; mi < 4; mi++) {
                ldsm_x4(sa_h + (u32)(mi * 1280) + ko, ah[mi]);
                ldsm_x4(sa_l + (u32)(mi * 1280) + ko, al[mi]);
            }
            #pragma unroll
            for (int nb = 0; nb < 2; nb++)
                ldsm_x4(sb_h + (u32)(nb * 1280) + ko, bb[nb]);
            #pragma unroll
            for (int mi = 0; mi < 4; mi++)
                #pragma unroll
                for (int ni = 0; ni < 4; ni++) {
                    mma_bf16(c[mi][ni], ah[mi], &bb[ni >> 1][(ni & 1) * 2]);
                    mma_bf16(c[mi][ni], al[mi], &bb[ni >> 1][(ni & 1) * 2]);
                }
            #pragma unroll
            for (int nb = 0; nb < 2; nb++)
                ldsm_x4(sb_l + (u32)(nb * 1280) + ko, bb[nb]);
            #pragma unroll
            for (int mi = 0; mi < 4; mi++)
                #pragma unroll
                for (int ni = 0; ni < 4; ni++)
                    mma_bf16(c[mi][ni], ah[mi], &bb[ni >> 1][(ni & 1) * 2]);
        }
        __syncthreads();
    }

    // ---- epilogue ----
    const int r0 = wm*64 + (lane >> 2);
    const int cc0 = wn*32 + (lane & 3)*2;

    #pragma unroll
    for (int mi = 0; mi < 4; mi++) {
        #pragma unroll
        for (int half = 0; half < 2; half++) {
            const size_t orow = arow + r0 + mi*16 + half*8;
            #pragma unroll
            for (int ni = 0; ni < 4; ni++) {
                const size_t ncol = brow + cc0 + ni*8;
                float v0 = c[mi][ni][half*2+0] + bias[ncol];
                float v1 = c[mi][ni][half*2+1] + bias[ncol+1];
                if (mode == 2) {
                    v0 = fmaxf(v0, 0.f); v1 = fmaxf(v1, 0.f);
                    __nv_bfloat16 h0,l0,h1,l1;
                    split2(v0,h0,l0); split2(v1,h1,l1);
                    __nv_bfloat162 p;
                    p.x=h0; p.y=h1; *(__nv_bfloat162*)(oh + orow*(size_t)Ntot + ncol) = p;
                    p.x=l0; p.y=l1; *(__nv_bfloat162*)(ol + orow*(size_t)Ntot + ncol) = p;
                } else if (mode == 3) {
                    const float* rp = resid + orow*(size_t)Ntot + ncol;
                    float2 o; o.x = v0 + rp[0]; o.y = v1 + rp[1];
                    *(float2*)(outf + orow*(size_t)Ntot + ncol) = o;
                } else {
                    float2 o; o.x = v0; o.y = v1;
                    *(float2*)(outf + orow*(size_t)Ntot + ncol) = o;
                }
            }
        }
    }
}

// ======================= attention core (fp32, shuffle-based) =======================
#define AQ_STR 52
#define ASM_FLOATS (3*AQ_STR*TT)

__global__ __launch_bounds__(512) void attn_kernel(int nb)
{
    extern __shared__ float sma[];
    float* sQ = sma;
    float* sK = sQ + TT*AQ_STR;
    float* sV = sK + TT*AQ_STR;

    const int tid = threadIdx.x;
    const int b   = blockIdx.x;
    const int t0  = tid >> 3;       // row 0..63
    const int g   = tid & 7;        // group 0..7
    const int e6  = g * 6;
    const int lane = tid & 31;
    const int gbase = lane & 24;    // 8-lane group base within warp
    const float kScale = 0.14433756729740643f;   // 48^-0.5
    const size_t rowbase = (size_t)(b*TT + t0);

    for (int h = 0; h < NH; h++) {
        __syncthreads();   // protect previous iteration's smem reads
        {
            const float* src = g_qkv + rowbase * NQKV + h*144 + e6;
            #pragma unroll
            for (int p = 0; p < 3; p++) {
                float2 q2 = *(const float2*)(src +       2*p);
                float2 k2 = *(const float2*)(src + 48  + 2*p);
                float2 v2 = *(const float2*)(src + 96  + 2*p);
                sQ[t0*AQ_STR + e6 + 2*p] = q2.x; sQ[t0*AQ_STR + e6 + 2*p + 1] = q2.y;
                sK[t0*AQ_STR + e6 + 2*p] = k2.x; sK[t0*AQ_STR + e6 + 2*p + 1] = k2.y;
                sV[t0*AQ_STR + e6 + 2*p] = v2.x; sV[t0*AQ_STR + e6 + 2*p + 1] = v2.y;
            }
        }
        __syncthreads();

        // register-cache full q row (24 u64)
        u64 qreg[24];
        {
            const float* qrow = sQ + t0*AQ_STR;
            #pragma unroll
            for (int i = 0; i < 24; i++) qreg[i] = *(const u64*)(qrow + 2*i);
        }

        // scores: thread owns cols s = g + 8k
        float sc[8];
        float mx = -1e30f;
        #pragma unroll
        for (int kk = 0; kk < 8; kk++) {
            const int s = g + 8*kk;
            float val = -1e30f;
            if (s <= t0) {
                u64 a = 0ull;
                const float* krow = sK + s*AQ_STR;
                #pragma unroll
                for (int i = 0; i < 24; i++)
                    a = fma2(qreg[i], *(const u64*)(krow + 2*i), a);
                float2 f = unp2(a);
                val = (f.x + f.y) * kScale;
                mx = fmaxf(mx, val);
            }
            sc[kk] = val;
        }
        // row max over the 8-lane group
        #pragma unroll
        for (int o = 4; o > 0; o >>= 1)
            mx = fmaxf(mx, __shfl_xor_sync(0xffffffffu, mx, o));
        // exp + row sum
        float lsum = 0.f;
        #pragma unroll
        for (int kk = 0; kk < 8; kk++) {
            const int s = g + 8*kk;
            const float e = (s <= t0) ? __expf(sc[kk] - mx) : 0.f;
            sc[kk] = e;
            lsum += e;
        }
        #pragma unroll
        for (int o = 4; o > 0; o >>= 1)
            lsum += __shfl_xor_sync(0xffffffffu, lsum, o);
        const float inv = 1.0f / lsum;
        #pragma unroll
        for (int kk = 0; kk < 8; kk++) sc[kk] *= inv;

        // P @ V via shuffle-broadcast of probs
        u64 oa[3] = {0ull, 0ull, 0ull};
        #pragma unroll 8
        for (int s = 0; s < TT; s++) {
            const float p = __shfl_sync(0xffffffffu, sc[s >> 3], gbase | (s & 7));
            const u64 pb = bc2(p);
            const float* vrow = sV + s*AQ_STR + e6;
            #pragma unroll
            for (int i = 0; i < 3; i++)
                oa[i] = fma2(pb, *(const u64*)(vrow + 2*i), oa[i]);
        }
        {
            __nv_bfloat16* dh = g_at_hi + rowbase * DD + h*HS + e6;
            __nv_bfloat16* dl = g_at_lo + rowbase * DD + h*HS + e6;
            #pragma unroll
            for (int p = 0; p < 3; p++) {
                float2 f = unp2(oa[p]);
                __nv_bfloat16 h0,l0,h1,l1;
                split2(f.x,h0,l0); split2(f.y,h1,l1);
                __nv_bfloat162 ph; ph.x=h0; ph.y=h1;
                __nv_bfloat162 pl; pl.x=l0; pl.y=l1;
                *(__nv_bfloat162*)(dh + 2*p) = ph;
                *(__nv_bfloat162*)(dl + 2*p) = pl;
            }
        }
    }
}

// ======================= host launcher =======================
template <typename T>
static void* sym_addr(T& sym) { void* p = nullptr; cudaGetSymbolAddress(&p, sym); return p; }

extern "C" void kernel_launch(void* const* d_in, const int* in_sizes, int n_in,
                              void* d_out, int out_size) {
    const float* x   = (const float*)d_in[0];
    const float* wq  = (const float*)d_in[1];
    const float* bq  = (const float*)d_in[2];
    const float* wk  = (const float*)d_in[3];
    const float* bk  = (const float*)d_in[4];
    const float* wv  = (const float*)d_in[5];
    const float* bv  = (const float*)d_in[6];
    const float* wo  = (const float*)d_in[7];
    const float* bo  = (const float*)d_in[8];
    const float* w1  = (const float*)d_in[9];
    const float* b1  = (const float*)d_in[10];
    const float* w2  = (const float*)d_in[11];
    const float* b2  = (const float*)d_in[12];
    const float* g1  = (const float*)d_in[13];
    const float* be1 = (const float*)d_in[14];
    const float* g2  = (const float*)d_in[15];
    const float* be2 = (const float*)d_in[16];
    float* out = (float*)d_out;

    const int nb = in_sizes[0] / (TT * DD);
    const int M  = nb * TT;
    const int Mtiles = M / 128;

    float* p_h      = (float*)sym_addr(g_h);
    __nv_bfloat16* p_h_hi = (__nv_bfloat16*)sym_addr(g_h_hi);
    __nv_bfloat16* p_h_lo = (__nv_bfloat16*)sym_addr(g_h_lo);
    float* p_qkv    = (float*)sym_addr(g_qkv);
    __nv_bfloat16* p_at_hi = (__nv_bfloat16*)sym_addr(g_at_hi);
    __nv_bfloat16* p_at_lo = (__nv_bfloat16*)sym_addr(g_at_lo);
    float* p_s      = (float*)sym_addr(g_s);
    float* p_h2     = (float*)sym_addr(g_h2);
    __nv_bfloat16* p_h2_hi = (__nv_bfloat16*)sym_addr(g_h2_hi);
    __nv_bfloat16* p_h2_lo = (__nv_bfloat16*)sym_addr(g_h2_lo);
    __nv_bfloat16* p_r_hi  = (__nv_bfloat16*)sym_addr(g_r_hi);
    __nv_bfloat16* p_r_lo  = (__nv_bfloat16*)sym_addr(g_r_lo);
    __nv_bfloat16* p_wqkv_h = (__nv_bfloat16*)sym_addr(g_wqkv_h);
    __nv_bfloat16* p_wqkv_l = (__nv_bfloat16*)sym_addr(g_wqkv_l);
    __nv_bfloat16* p_wot_h  = (__nv_bfloat16*)sym_addr(g_wot_h);
    __nv_bfloat16* p_wot_l  = (__nv_bfloat16*)sym_addr(g_wot_l);
    __nv_bfloat16* p_w1t_h  = (__nv_bfloat16*)sym_addr(g_w1t_h);
    __nv_bfloat16* p_w1t_l  = (__nv_bfloat16*)sym_addr(g_w1t_l);
    __nv_bfloat16* p_w2t_h  = (__nv_bfloat16*)sym_addr(g_w2t_h);
    __nv_bfloat16* p_w2t_l  = (__nv_bfloat16*)sym_addr(g_w2t_l);
    float* p_bqkv   = (float*)sym_addr(g_bqkv);

    cudaFuncSetAttribute(gemm_kernel, cudaFuncAttributeMaxDynamicSharedMemorySize, GSM_TOTAL);
    cudaFuncSetAttribute(attn_kernel, cudaFuncAttributeMaxDynamicSharedMemorySize,
                         (int)(ASM_FLOATS * sizeof(float)));

    // 1. weight split / transpose
    split_weights_kernel<<<1024, 256>>>(wq, bq, wk, bk, wv, bv, wo, w1, w2);

    // 2. LN1
    ln_kernel<<<M/8, 256>>>(x, nullptr, g1, be1, p_h, p_h_hi, p_h_lo, M);

    // 3. QKV GEMM
    gemm_kernel<<<Mtiles*9, 256, GSM_TOTAL>>>(
        p_h_hi, p_h_lo, p_wqkv_h, p_wqkv_l, p_bqkv, nullptr,
        p_qkv, nullptr, nullptr, DD, 9, NQKV, 0);

    // 4. attention core
    attn_kernel<<<nb, 512, ASM_FLOATS * sizeof(float)>>>(nb);

    // 5. wo GEMM
    gemm_kernel<<<Mtiles*3, 256, GSM_TOTAL>>>(
        p_at_hi, p_at_lo, p_wot_h, p_wot_l, bo, nullptr,
        p_s, nullptr, nullptr, DD, 3, DD, 0);

    // 6. LN2
    ln_kernel<<<M/8, 256>>>(p_h, p_s, g2, be2, p_h2, p_h2_hi, p_h2_lo, M);

    // 7. FF1
    gemm_kernel<<<Mtiles*12, 256, GSM_TOTAL>>>(
        p_h2_hi, p_h2_lo, p_w1t_h, p_w1t_l, b1, nullptr,
        nullptr, p_r_hi, p_r_lo, DD, 12, FFD, 2);

    // 8. FF2
    gemm_kernel<<<Mtiles*3, 256, GSM_TOTAL>>>(
        p_r_hi, p_r_lo, p_w2t_h, p_w2t_l, b2, p_h2,
        out, nullptr, nullptr, FFD, 3, DD, 3);
}

// round 9
// speedup vs baseline: 4.2142x; 1.2805x over previous
#include <cuda_runtime.h>
#include <cuda_fp16.h>
#include <cstdint>

#define TT 64
#define DD 384
#define NH 8
#define HS 48
#define FFD 1536
#define NQKV 1152
#define NBMAX 2048
#define MROWS (NBMAX*TT)

typedef unsigned long long u64;
typedef unsigned int u32;

// ======================= device scratch buffers =======================
__device__ __half g_wqkv[NQKV*DD];
__device__ __half g_wot[DD*DD];
__device__ __half g_w1t[FFD*DD];
__device__ __half g_w2t[DD*FFD];
__device__ float g_bqkv[NQKV];
__device__ float g_h[(size_t)MROWS*DD];
__device__ __half g_h_hi[(size_t)MROWS*DD], g_h_lo[(size_t)MROWS*DD];
__device__ float g_qkv[(size_t)MROWS*NQKV];
__device__ __half g_at_hi[(size_t)MROWS*DD], g_at_lo[(size_t)MROWS*DD];
__device__ float g_s[(size_t)MROWS*DD];
__device__ float g_h2[(size_t)MROWS*DD];
__device__ __half g_h2_hi[(size_t)MROWS*DD], g_h2_lo[(size_t)MROWS*DD];
__device__ __half g_r_hi[(size_t)MROWS*FFD], g_r_lo[(size_t)MROWS*FFD];

// ======================= helpers =======================
__device__ __forceinline__ u64 pack2(float lo, float hi) {
    u64 r; asm("mov.b64 %0, {%1, %2};" : "=l"(r) : "f"(lo), "f"(hi)); return r;
}
__device__ __forceinline__ u64 bc2(float v) { return pack2(v, v); }
__device__ __forceinline__ float2 unp2(u64 v) {
    float2 f; asm("mov.b64 {%0, %1}, %2;" : "=f"(f.x), "=f"(f.y) : "l"(v)); return f;
}
__device__ __forceinline__ u64 fma2(u64 a, u64 b, u64 c) {
    u64 d; asm("fma.rn.f32x2 %0, %1, %2, %3;" : "=l"(d) : "l"(a), "l"(b), "l"(c)); return d;
}
__device__ __forceinline__ void split2h(float x, __half& hi, __half& lo) {
    hi = __float2half_rn(x);
    lo = __float2half_rn(x - __half2float(hi));
}
__device__ __forceinline__ u32 smem_u32(const void* p) {
    u32 a; asm("{ .reg .u64 t; cvta.to.shared.u64 t, %1; cvt.u32.u64 %0, t; }" : "=r"(a) : "l"(p));
    return a;
}
__device__ __forceinline__ void cp16(u32 dst, const void* src) {
    asm volatile("cp.async.cg.shared.global [%0], [%1], 16;" :: "r"(dst), "l"(src));
}
#define CP_COMMIT()  asm volatile("cp.async.commit_group;" ::: "memory")
#define CP_WAIT(n)   asm volatile("cp.async.wait_group %0;" :: "n"(n) : "memory")

__device__ __forceinline__ void ldsm_x4(u32 addr, u32* r) {
    asm volatile("ldmatrix.sync.aligned.m8n8.x4.shared.b16 {%0,%1,%2,%3}, [%4];"
        : "=r"(r[0]), "=r"(r[1]), "=r"(r[2]), "=r"(r[3]) : "r"(addr));
}
__device__ __forceinline__ void mma_f16(float* c, const u32* a, const u32* b) {
    asm volatile("mma.sync.aligned.m16n8k16.row.col.f32.f16.f16.f32 "
        "{%0,%1,%2,%3}, {%4,%5,%6,%7}, {%8,%9}, {%0,%1,%2,%3};"
        : "+f"(c[0]), "+f"(c[1]), "+f"(c[2]), "+f"(c[3])
        : "r"(a[0]), "r"(a[1]), "r"(a[2]), "r"(a[3]), "r"(b[0]), "r"(b[1]));
}

// ======================= weight fp16 convert / transpose =======================
__global__ void split_weights_kernel(
    const float* __restrict__ wq, const float* __restrict__ bq,
    const float* __restrict__ wk, const float* __restrict__ bk,
    const float* __restrict__ wv, const float* __restrict__ bv,
    const float* __restrict__ wo, const float* __restrict__ w1,
    const float* __restrict__ w2)
{
    const int stride = gridDim.x * blockDim.x;
    const int t0 = blockIdx.x * blockDim.x + threadIdx.x;
    for (int i = t0; i < NQKV*DD; i += stride) {
        int n = i / DD, k = i - n*DD;
        int h = n / 144, rm = n - h*144, m = rm / 48, e = rm - m*48;
        const float* src = (m==0) ? wq : ((m==1) ? wk : wv);
        g_wqkv[i] = __float2half_rn(src[((size_t)(h*DD + k))*HS + e]);
    }
    for (int i = t0; i < DD*DD; i += stride) {
        int n = i / DD, k = i - n*DD;
        g_wot[i] = __float2half_rn(wo[(size_t)k*DD + n]);
    }
    for (int i = t0; i < FFD*DD; i += stride) {
        int n = i / DD, k = i - n*DD;
        g_w1t[i] = __float2half_rn(w1[(size_t)k*FFD + n]);
    }
    for (int i = t0; i < DD*FFD; i += stride) {
        int n = i / FFD, k = i - n*FFD;
        g_w2t[i] = __float2half_rn(w2[(size_t)k*DD + n]);
    }
    for (int i = t0; i < NQKV; i += stride) {
        int h = i / 144, rm = i - h*144, m = rm / 48, e = rm - m*48;
        g_bqkv[i] = (m==0 ? bq : (m==1 ? bk : bv))[h*HS + e];
    }
}

// ======================= layernorm (+optional add) + fp16 split =======================
__global__ __launch_bounds__(256) void ln_kernel(
    const float* __restrict__ in1, const float* __restrict__ in2,
    const float* __restrict__ gg, const float* __restrict__ bb,
    float* __restrict__ outf, __half* __restrict__ oh, __half* __restrict__ ol,
    int nrows)
{
    int r = blockIdx.x*8 + (threadIdx.x >> 5);
    int l = threadIdx.x & 31;
    if (r >= nrows) return;
    size_t ro = (size_t)r * DD;
    float v[12]; float s1 = 0.f, s2 = 0.f;
    #pragma unroll
    for (int jt = 0; jt < 3; jt++) {
        int c = jt*128 + 4*l;
        float4 a = *(const float4*)(in1 + ro + c);
        if (in2) {
            float4 b = *(const float4*)(in2 + ro + c);
            a.x += b.x; a.y += b.y; a.z += b.z; a.w += b.w;
        }
        v[4*jt+0]=a.x; v[4*jt+1]=a.y; v[4*jt+2]=a.z; v[4*jt+3]=a.w;
    }
    #pragma unroll
    for (int i = 0; i < 12; i++) { s1 += v[i]; s2 += v[i]*v[i]; }
    #pragma unroll
    for (int o = 16; o > 0; o >>= 1) {
        s1 += __shfl_xor_sync(0xffffffffu, s1, o);
        s2 += __shfl_xor_sync(0xffffffffu, s2, o);
    }
    float mean = s1 * (1.0f/384.0f);
    float var  = s2 * (1.0f/384.0f) - mean*mean;
    float rstd = rsqrtf(var + 1e-5f);
    #pragma unroll
    for (int jt = 0; jt < 3; jt++) {
        int c = jt*128 + 4*l;
        float4 gv = *(const float4*)(gg + c);
        float4 bv = *(const float4*)(bb + c);
        float y0 = (v[4*jt+0]-mean)*rstd*gv.x + bv.x;
        float y1 = (v[4*jt+1]-mean)*rstd*gv.y + bv.y;
        float y2 = (v[4*jt+2]-mean)*rstd*gv.z + bv.z;
        float y3 = (v[4*jt+3]-mean)*rstd*gv.w + bv.w;
        *(float4*)(outf + ro + c) = make_float4(y0, y1, y2, y3);
        __half h0,l0,h1,l1,h2,l2,h3,l3;
        split2h(y0,h0,l0); split2h(y1,h1,l1); split2h(y2,h2,l2); split2h(y3,h3,l3);
        __half2 p;
        p.x=h0; p.y=h1; *(__half2*)(oh + ro + c)     = p;
        p.x=h2; p.y=h3; *(__half2*)(oh + ro + c + 2) = p;
        p.x=l0; p.y=l1; *(__half2*)(ol + ro + c)     = p;
        p.x=l2; p.y=l3; *(__half2*)(ol + ro + c + 2) = p;
    }
}

// ======================= split GEMM via mma.sync (HMMA fp16, 2 products) =======================
// D = (Ah + Al) @ Bh^T ; 3 smem arrays per stage (Ah, Al, Bh), row stride 80 B.
#define ARR_BYTES 10240                  // 128 rows * 80 B
#define STG_BYTES (3*ARR_BYTES)          // 30720
#define GSM_TOTAL (2*STG_BYTES)          // 61440

__global__ __launch_bounds__(256, 2) void gemm_kernel(
    const __half* __restrict__ Ah, const __half* __restrict__ Al,
    const __half* __restrict__ Bh,
    const float* __restrict__ bias, const float* __restrict__ resid,
    float* __restrict__ outf, __half* __restrict__ oh, __half* __restrict__ ol,
    int K, int Ntiles, int Ntot, int mode)
{
    extern __shared__ char smem[];
    const u32 smem_base = smem_u32(smem);
    const int tid = threadIdx.x;
    const int wid = tid >> 5;
    const int lane = tid & 31;

    const int mt = blockIdx.x / Ntiles;
    const int nt = blockIdx.x - mt * Ntiles;
    const size_t arow = (size_t)mt * 128;
    const size_t brow = (size_t)nt * 128;

    const __half* Abase_h = Ah + arow * (size_t)K;
    const __half* Abase_l = Al + arow * (size_t)K;
    const __half* Bbase_h = Bh + brow * (size_t)K;

    const int wm = wid & 1;    // 2 m-blocks of 64
    const int wn = wid >> 1;   // 4 n-blocks of 32

    const u32 a_off = (u32)((wm*64 + (lane & 15)) * 80 + (lane >> 4) * 16);
    const u32 b_off = (u32)((wn*32 + ((lane & 7) | ((lane >> 1) & 8))) * 80
                            + ((lane >> 3) & 1) * 16);

    float c[4][4][4];
    #pragma unroll
    for (int mi = 0; mi < 4; mi++)
        #pragma unroll
        for (int ni = 0; ni < 4; ni++)
            #pragma unroll
            for (int j = 0; j < 4; j++) c[mi][ni][j] = 0.f;

    const int nc = K >> 5;   // K/32 chunks

    auto load_chunk = [&](int stage, int cc) {
        const u32 sb = smem_base + stage * STG_BYTES;
        const int c0 = cc << 5;
        #pragma unroll
        for (int i = 0; i < 6; i++) {
            int s = tid + (i << 8);
            int arr = s >> 9;              // 0..2
            int within = s & 511;
            int r   = within >> 2;
            int c16 = within & 3;
            const __half* bp = (arr == 0) ? Abase_h : (arr == 1) ? Abase_l : Bbase_h;
            const void* src = bp + (size_t)r * K + c0 + (c16 << 3);
            u32 dst = sb + arr * ARR_BYTES + (u32)(r * 80 + (c16 << 4));
            cp16(dst, src);
        }
        CP_COMMIT();
    };

    load_chunk(0, 0);
    for (int cc = 0; cc < nc; cc++) {
        const int cur = cc & 1;
        if (cc + 1 < nc) { load_chunk((cc + 1) & 1, cc + 1); CP_WAIT(1); }
        else             { CP_WAIT(0); }
        __syncthreads();

        const u32 sb = smem_base + cur * STG_BYTES;
        const u32 sa_h = sb + a_off;
        const u32 sa_l = sb + ARR_BYTES   + a_off;
        const u32 sb_h = sb + 2*ARR_BYTES + b_off;

        #pragma unroll
        for (int ks = 0; ks < 2; ks++) {
            const u32 ko = (u32)(ks * 32);     // 16 cols * 2B
            u32 ah[4][4], al[4][4], bb[2][4];
            #pragma unroll
            for (int mi = 0; mi < 4; mi++) {
                ldsm_x4(sa_h + (u32)(mi * 1280) + ko, ah[mi]);
                ldsm_x4(sa_l + (u32)(mi * 1280) + ko, al[mi]);
            }
            #pragma unroll
            for (int nb = 0; nb < 2; nb++)
                ldsm_x4(sb_h + (u32)(nb * 1280) + ko, bb[nb]);
            #pragma unroll
            for (int mi = 0; mi < 4; mi++)
                #pragma unroll
                for (int ni = 0; ni < 4; ni++) {
                    mma_f16(c[mi][ni], ah[mi], &bb[ni >> 1][(ni & 1) * 2]);
                    mma_f16(c[mi][ni], al[mi], &bb[ni >> 1][(ni & 1) * 2]);
                }
        }
        __syncthreads();
    }

    // ---- epilogue ----
    const int r0 = wm*64 + (lane >> 2);
    const int cc0 = wn*32 + (lane & 3)*2;

    #pragma unroll
    for (int mi = 0; mi < 4; mi++) {
        #pragma unroll
        for (int half = 0; half < 2; half++) {
            const size_t orow = arow + r0 + mi*16 + half*8;
            #pragma unroll
            for (int ni = 0; ni < 4; ni++) {
                const size_t ncol = brow + cc0 + ni*8;
                float v0 = c[mi][ni][half*2+0] + bias[ncol];
                float v1 = c[mi][ni][half*2+1] + bias[ncol+1];
                if (mode == 2) {
                    v0 = fmaxf(v0, 0.f); v1 = fmaxf(v1, 0.f);
                    __half h0,l0,h1,l1;
                    split2h(v0,h0,l0); split2h(v1,h1,l1);
                    __half2 p;
                    p.x=h0; p.y=h1; *(__half2*)(oh + orow*(size_t)Ntot + ncol) = p;
                    p.x=l0; p.y=l1; *(__half2*)(ol + orow*(size_t)Ntot + ncol) = p;
                } else if (mode == 3) {
                    const float* rp = resid + orow*(size_t)Ntot + ncol;
                    float2 o; o.x = v0 + rp[0]; o.y = v1 + rp[1];
                    *(float2*)(outf + orow*(size_t)Ntot + ncol) = o;
                } else {
                    float2 o; o.x = v0; o.y = v1;
                    *(float2*)(outf + orow*(size_t)Ntot + ncol) = o;
                }
            }
        }
    }
}

// ======================= attention core (fp32, shuffle-based) =======================
#define AQ_STR 52
#define ASM_FLOATS (3*AQ_STR*TT)

__global__ __launch_bounds__(512) void attn_kernel(int nb)
{
    extern __shared__ float sma[];
    float* sQ = sma;
    float* sK = sQ + TT*AQ_STR;
    float* sV = sK + TT*AQ_STR;

    const int tid = threadIdx.x;
    const int b   = blockIdx.x;
    const int t0  = tid >> 3;       // row 0..63
    const int g   = tid & 7;        // group 0..7
    const int e6  = g * 6;
    const int lane = tid & 31;
    const int gbase = lane & 24;    // 8-lane group base within warp
    const float kScale = 0.14433756729740643f;   // 48^-0.5
    const size_t rowbase = (size_t)(b*TT + t0);

    for (int h = 0; h < NH; h++) {
        __syncthreads();   // protect previous iteration's smem reads
        {
            const float* src = g_qkv + rowbase * NQKV + h*144 + e6;
            #pragma unroll
            for (int p = 0; p < 3; p++) {
                float2 q2 = *(const float2*)(src +       2*p);
                float2 k2 = *(const float2*)(src + 48  + 2*p);
                float2 v2 = *(const float2*)(src + 96  + 2*p);
                sQ[t0*AQ_STR + e6 + 2*p] = q2.x; sQ[t0*AQ_STR + e6 + 2*p + 1] = q2.y;
                sK[t0*AQ_STR + e6 + 2*p] = k2.x; sK[t0*AQ_STR + e6 + 2*p + 1] = k2.y;
                sV[t0*AQ_STR + e6 + 2*p] = v2.x; sV[t0*AQ_STR + e6 + 2*p + 1] = v2.y;
            }
        }
        __syncthreads();

        // register-cache full q row (24 u64)
        u64 qreg[24];
        {
            const float* qrow = sQ + t0*AQ_STR;
            #pragma unroll
            for (int i = 0; i < 24; i++) qreg[i] = *(const u64*)(qrow + 2*i);
        }

        // scores: thread owns cols s = g + 8k
        float sc[8];
        float mx = -1e30f;
        #pragma unroll
        for (int kk = 0; kk < 8; kk++) {
            const int s = g + 8*kk;
            float val = -1e30f;
            if (s <= t0) {
                u64 a = 0ull;
                const float* krow = sK + s*AQ_STR;
                #pragma unroll
                for (int i = 0; i < 24; i++)
                    a = fma2(qreg[i], *(const u64*)(krow + 2*i), a);
                float2 f = unp2(a);
                val = (f.x + f.y) * kScale;
                mx = fmaxf(mx, val);
            }
            sc[kk] = val;
        }
        #pragma unroll
        for (int o = 4; o > 0; o >>= 1)
            mx = fmaxf(mx, __shfl_xor_sync(0xffffffffu, mx, o));
        float lsum = 0.f;
        #pragma unroll
        for (int kk = 0; kk < 8; kk++) {
            const int s = g + 8*kk;
            const float e = (s <= t0) ? __expf(sc[kk] - mx) : 0.f;
            sc[kk] = e;
            lsum += e;
        }
        #pragma unroll
        for (int o = 4; o > 0; o >>= 1)
            lsum += __shfl_xor_sync(0xffffffffu, lsum, o);
        const float inv = 1.0f / lsum;
        #pragma unroll
        for (int kk = 0; kk < 8; kk++) sc[kk] *= inv;

        // P @ V via shuffle-broadcast of probs
        u64 oa[3] = {0ull, 0ull, 0ull};
        #pragma unroll 8
        for (int s = 0; s < TT; s++) {
            const float p = __shfl_sync(0xffffffffu, sc[s >> 3], gbase | (s & 7));
            const u64 pb = bc2(p);
            const float* vrow = sV + s*AQ_STR + e6;
            #pragma unroll
            for (int i = 0; i < 3; i++)
                oa[i] = fma2(pb, *(const u64*)(vrow + 2*i), oa[i]);
        }
        {
            __half* dh = g_at_hi + rowbase * DD + h*HS + e6;
            __half* dl = g_at_lo + rowbase * DD + h*HS + e6;
            #pragma unroll
            for (int p = 0; p < 3; p++) {
                float2 f = unp2(oa[p]);
                __half h0,l0,h1,l1;
                split2h(f.x,h0,l0); split2h(f.y,h1,l1);
                __half2 ph; ph.x=h0; ph.y=h1;
                __half2 pl; pl.x=l0; pl.y=l1;
                *(__half2*)(dh + 2*p) = ph;
                *(__half2*)(dl + 2*p) = pl;
            }
        }
    }
}

// ======================= host launcher =======================
template <typename T>
static void* sym_addr(T& sym) { void* p = nullptr; cudaGetSymbolAddress(&p, sym); return p; }

extern "C" void kernel_launch(void* const* d_in, const int* in_sizes, int n_in,
                              void* d_out, int out_size) {
    const float* x   = (const float*)d_in[0];
    const float* wq  = (const float*)d_in[1];
    const float* bq  = (const float*)d_in[2];
    const float* wk  = (const float*)d_in[3];
    const float* bk  = (const float*)d_in[4];
    const float* wv  = (const float*)d_in[5];
    const float* bv  = (const float*)d_in[6];
    const float* wo  = (const float*)d_in[7];
    const float* bo  = (const float*)d_in[8];
    const float* w1  = (const float*)d_in[9];
    const float* b1  = (const float*)d_in[10];
    const float* w2  = (const float*)d_in[11];
    const float* b2  = (const float*)d_in[12];
    const float* g1  = (const float*)d_in[13];
    const float* be1 = (const float*)d_in[14];
    const float* g2  = (const float*)d_in[15];
    const float* be2 = (const float*)d_in[16];
    float* out = (float*)d_out;

    const int nb = in_sizes[0] / (TT * DD);
    const int M  = nb * TT;
    const int Mtiles = M / 128;

    float* p_h      = (float*)sym_addr(g_h);
    __half* p_h_hi  = (__half*)sym_addr(g_h_hi);
    __half* p_h_lo  = (__half*)sym_addr(g_h_lo);
    float* p_qkv    = (float*)sym_addr(g_qkv);
    __half* p_at_hi = (__half*)sym_addr(g_at_hi);
    __half* p_at_lo = (__half*)sym_addr(g_at_lo);
    float* p_s      = (float*)sym_addr(g_s);
    float* p_h2     = (float*)sym_addr(g_h2);
    __half* p_h2_hi = (__half*)sym_addr(g_h2_hi);
    __half* p_h2_lo = (__half*)sym_addr(g_h2_lo);
    __half* p_r_hi  = (__half*)sym_addr(g_r_hi);
    __half* p_r_lo  = (__half*)sym_addr(g_r_lo);
    __half* p_wqkv  = (__half*)sym_addr(g_wqkv);
    __half* p_wot   = (__half*)sym_addr(g_wot);
    __half* p_w1t   = (__half*)sym_addr(g_w1t);
    __half* p_w2t   = (__half*)sym_addr(g_w2t);
    float* p_bqkv   = (float*)sym_addr(g_bqkv);

    cudaFuncSetAttribute(gemm_kernel, cudaFuncAttributeMaxDynamicSharedMemorySize, GSM_TOTAL);
    cudaFuncSetAttribute(attn_kernel, cudaFuncAttributeMaxDynamicSharedMemorySize,
                         (int)(ASM_FLOATS * sizeof(float)));

    // 1. weight fp16 convert / transpose
    split_weights_kernel<<<1024, 256>>>(wq, bq, wk, bk, wv, bv, wo, w1, w2);

    // 2. LN1
    ln_kernel<<<M/8, 256>>>(x, nullptr, g1, be1, p_h, p_h_hi, p_h_lo, M);

    // 3. QKV GEMM
    gemm_kernel<<<Mtiles*9, 256, GSM_TOTAL>>>(
        p_h_hi, p_h_lo, p_wqkv, p_bqkv, nullptr,
        p_qkv, nullptr, nullptr, DD, 9, NQKV, 0);

    // 4. attention core
    attn_kernel<<<nb, 512, ASM_FLOATS * sizeof(float)>>>(nb);

    // 5. wo GEMM
    gemm_kernel<<<Mtiles*3, 256, GSM_TOTAL>>>(
        p_at_hi, p_at_lo, p_wot, bo, nullptr,
        p_s, nullptr, nullptr, DD, 3, DD, 0);

    // 6. LN2
    ln_kernel<<<M/8, 256>>>(p_h, p_s, g2, be2, p_h2, p_h2_hi, p_h2_lo, M);

    // 7. FF1
    gemm_kernel<<<Mtiles*12, 256, GSM_TOTAL>>>(
        p_h2_hi, p_h2_lo, p_w1t, b1, nullptr,
        nullptr, p_r_hi, p_r_lo, DD, 12, FFD, 2);

    // 8. FF2
    gemm_kernel<<<Mtiles*3, 256, GSM_TOTAL>>>(
        p_r_hi, p_r_lo, p_w2t, b2, p_h2,
        out, nullptr, nullptr, FFD, 3, DD, 3);
}

// round 11
// speedup vs baseline: 5.1123x; 1.2131x over previous
#include <cuda_runtime.h>
#include <cuda_fp16.h>
#include <cstdint>
#include <cstring>

#define TT 64
#define DD 384
#define NH 8
#define HS 48
#define FFD 1536
#define NQKV 1152
#define NBMAX 2048
#define MROWS (NBMAX*TT)

typedef unsigned long long u64;
typedef unsigned int u32;

// ======================= device scratch buffers =======================
__device__ __half g_wqkv[NQKV*DD];
__device__ __half g_wot[DD*DD];
__device__ __half g_w1t[FFD*DD];
__device__ __half g_w2t[DD*FFD];
__device__ float g_bqkv[NQKV];
__device__ float g_h[(size_t)MROWS*DD];
__device__ __half g_h_hi[(size_t)MROWS*DD], g_h_lo[(size_t)MROWS*DD];
__device__ __half g_qkv16[(size_t)MROWS*NQKV];
__device__ __half g_at_hi[(size_t)MROWS*DD], g_at_lo[(size_t)MROWS*DD];
__device__ float g_s[(size_t)MROWS*DD];
__device__ float g_h2[(size_t)MROWS*DD];
__device__ __half g_h2_hi[(size_t)MROWS*DD], g_h2_lo[(size_t)MROWS*DD];
__device__ __half g_r_hi[(size_t)MROWS*FFD], g_r_lo[(size_t)MROWS*FFD];

// ======================= helpers =======================
__device__ __forceinline__ void split2h(float x, __half& hi, __half& lo) {
    hi = __float2half_rn(x);
    lo = __float2half_rn(x - __half2float(hi));
}
__device__ __forceinline__ u32 h2u(float a, float b) {
    __half2 h = __floats2half2_rn(a, b);
    u32 r; memcpy(&r, &h, 4); return r;
}
__device__ __forceinline__ u32 smem_u32(const void* p) {
    u32 a; asm("{ .reg .u64 t; cvta.to.shared.u64 t, %1; cvt.u32.u64 %0, t; }" : "=r"(a) : "l"(p));
    return a;
}
__device__ __forceinline__ void cp16(u32 dst, const void* src) {
    asm volatile("cp.async.cg.shared.global [%0], [%1], 16;" :: "r"(dst), "l"(src));
}
#define CP_COMMIT()  asm volatile("cp.async.commit_group;" ::: "memory")
#define CP_WAIT(n)   asm volatile("cp.async.wait_group %0;" :: "n"(n) : "memory")

__device__ __forceinline__ void ldsm_x4(u32 addr, u32* r) {
    asm volatile("ldmatrix.sync.aligned.m8n8.x4.shared.b16 {%0,%1,%2,%3}, [%4];"
        : "=r"(r[0]), "=r"(r[1]), "=r"(r[2]), "=r"(r[3]) : "r"(addr));
}
__device__ __forceinline__ void ldsm_x4_t(u32 addr, u32* r) {
    asm volatile("ldmatrix.sync.aligned.m8n8.x4.trans.shared.b16 {%0,%1,%2,%3}, [%4];"
        : "=r"(r[0]), "=r"(r[1]), "=r"(r[2]), "=r"(r[3]) : "r"(addr));
}
__device__ __forceinline__ void mma_f16(float* c, const u32* a, const u32* b) {
    asm volatile("mma.sync.aligned.m16n8k16.row.col.f32.f16.f16.f32 "
        "{%0,%1,%2,%3}, {%4,%5,%6,%7}, {%8,%9}, {%0,%1,%2,%3};"
        : "+f"(c[0]), "+f"(c[1]), "+f"(c[2]), "+f"(c[3])
        : "r"(a[0]), "r"(a[1]), "r"(a[2]), "r"(a[3]), "r"(b[0]), "r"(b[1]));
}

// ======================= weight fp16 convert / transpose =======================
__global__ void split_weights_kernel(
    const float* __restrict__ wq, const float* __restrict__ bq,
    const float* __restrict__ wk, const float* __restrict__ bk,
    const float* __restrict__ wv, const float* __restrict__ bv,
    const float* __restrict__ wo, const float* __restrict__ w1,
    const float* __restrict__ w2)
{
    const int stride = gridDim.x * blockDim.x;
    const int t0 = blockIdx.x * blockDim.x + threadIdx.x;
    for (int i = t0; i < NQKV*DD; i += stride) {
        int n = i / DD, k = i - n*DD;
        int h = n / 144, rm = n - h*144, m = rm / 48, e = rm - m*48;
        const float* src = (m==0) ? wq : ((m==1) ? wk : wv);
        g_wqkv[i] = __float2half_rn(src[((size_t)(h*DD + k))*HS + e]);
    }
    for (int i = t0; i < DD*DD; i += stride) {
        int n = i / DD, k = i - n*DD;
        g_wot[i] = __float2half_rn(wo[(size_t)k*DD + n]);
    }
    for (int i = t0; i < FFD*DD; i += stride) {
        int n = i / DD, k = i - n*DD;
        g_w1t[i] = __float2half_rn(w1[(size_t)k*FFD + n]);
    }
    for (int i = t0; i < DD*FFD; i += stride) {
        int n = i / FFD, k = i - n*FFD;
        g_w2t[i] = __float2half_rn(w2[(size_t)k*DD + n]);
    }
    for (int i = t0; i < NQKV; i += stride) {
        int h = i / 144, rm = i - h*144, m = rm / 48, e = rm - m*48;
        g_bqkv[i] = (m==0 ? bq : (m==1 ? bk : bv))[h*HS + e];
    }
}

// ======================= layernorm (+optional add) + fp16 split =======================
__global__ __launch_bounds__(256) void ln_kernel(
    const float* __restrict__ in1, const float* __restrict__ in2,
    const float* __restrict__ gg, const float* __restrict__ bb,
    float* __restrict__ outf, __half* __restrict__ oh, __half* __restrict__ ol,
    int nrows)
{
    int r = blockIdx.x*8 + (threadIdx.x >> 5);
    int l = threadIdx.x & 31;
    if (r >= nrows) return;
    size_t ro = (size_t)r * DD;
    float v[12]; float s1 = 0.f, s2 = 0.f;
    #pragma unroll
    for (int jt = 0; jt < 3; jt++) {
        int c = jt*128 + 4*l;
        float4 a = *(const float4*)(in1 + ro + c);
        if (in2) {
            float4 b = *(const float4*)(in2 + ro + c);
            a.x += b.x; a.y += b.y; a.z += b.z; a.w += b.w;
        }
        v[4*jt+0]=a.x; v[4*jt+1]=a.y; v[4*jt+2]=a.z; v[4*jt+3]=a.w;
    }
    #pragma unroll
    for (int i = 0; i < 12; i++) { s1 += v[i]; s2 += v[i]*v[i]; }
    #pragma unroll
    for (int o = 16; o > 0; o >>= 1) {
        s1 += __shfl_xor_sync(0xffffffffu, s1, o);
        s2 += __shfl_xor_sync(0xffffffffu, s2, o);
    }
    float mean = s1 * (1.0f/384.0f);
    float var  = s2 * (1.0f/384.0f) - mean*mean;
    float rstd = rsqrtf(var + 1e-5f);
    #pragma unroll
    for (int jt = 0; jt < 3; jt++) {
        int c = jt*128 + 4*l;
        float4 gv = *(const float4*)(gg + c);
        float4 bv = *(const float4*)(bb + c);
        float y0 = (v[4*jt+0]-mean)*rstd*gv.x + bv.x;
        float y1 = (v[4*jt+1]-mean)*rstd*gv.y + bv.y;
        float y2 = (v[4*jt+2]-mean)*rstd*gv.z + bv.z;
        float y3 = (v[4*jt+3]-mean)*rstd*gv.w + bv.w;
        *(float4*)(outf + ro + c) = make_float4(y0, y1, y2, y3);
        __half h0,l0,h1,l1,h2,l2,h3,l3;
        split2h(y0,h0,l0); split2h(y1,h1,l1); split2h(y2,h2,l2); split2h(y3,h3,l3);
        __half2 p;
        p.x=h0; p.y=h1; *(__half2*)(oh + ro + c)     = p;
        p.x=h2; p.y=h3; *(__half2*)(oh + ro + c + 2) = p;
        p.x=l0; p.y=l1; *(__half2*)(ol + ro + c)     = p;
        p.x=l2; p.y=l3; *(__half2*)(ol + ro + c + 2) = p;
    }
}

// ======================= split GEMM via mma.sync (HMMA fp16, 2 products) =======================
// mode 0: outf = D + bias
// mode 2: (oh,ol) = split(relu(D + bias))
// mode 3: outf = D + bias + resid
// mode 4: oh = fp16(D + bias)
#define ARR_BYTES 10240
#define STG_BYTES (3*ARR_BYTES)
#define GSM_TOTAL (2*STG_BYTES)

__global__ __launch_bounds__(256, 2) void gemm_kernel(
    const __half* __restrict__ Ah, const __half* __restrict__ Al,
    const __half* __restrict__ Bh,
    const float* __restrict__ bias, const float* __restrict__ resid,
    float* __restrict__ outf, __half* __restrict__ oh, __half* __restrict__ ol,
    int K, int Ntiles, int Ntot, int mode)
{
    extern __shared__ char smem[];
    const u32 smem_base = smem_u32(smem);
    const int tid = threadIdx.x;
    const int wid = tid >> 5;
    const int lane = tid & 31;

    const int mt = blockIdx.x / Ntiles;
    const int nt = blockIdx.x - mt * Ntiles;
    const size_t arow = (size_t)mt * 128;
    const size_t brow = (size_t)nt * 128;

    const __half* Abase_h = Ah + arow * (size_t)K;
    const __half* Abase_l = Al + arow * (size_t)K;
    const __half* Bbase_h = Bh + brow * (size_t)K;

    const int wm = wid & 1;
    const int wn = wid >> 1;

    const u32 a_off = (u32)((wm*64 + (lane & 15)) * 80 + (lane >> 4) * 16);
    const u32 b_off = (u32)((wn*32 + ((lane & 7) | ((lane >> 1) & 8))) * 80
                            + ((lane >> 3) & 1) * 16);

    float c[4][4][4];
    #pragma unroll
    for (int mi = 0; mi < 4; mi++)
        #pragma unroll
        for (int ni = 0; ni < 4; ni++)
            #pragma unroll
            for (int j = 0; j < 4; j++) c[mi][ni][j] = 0.f;

    const int nc = K >> 5;

    auto load_chunk = [&](int stage, int cc) {
        const u32 sb = smem_base + stage * STG_BYTES;
        const int c0 = cc << 5;
        #pragma unroll
        for (int i = 0; i < 6; i++) {
            int s = tid + (i << 8);
            int arr = s >> 9;
            int within = s & 511;
            int r   = within >> 2;
            int c16 = within & 3;
            const __half* bp = (arr == 0) ? Abase_h : (arr == 1) ? Abase_l : Bbase_h;
            const void* src = bp + (size_t)r * K + c0 + (c16 << 3);
            u32 dst = sb + arr * ARR_BYTES + (u32)(r * 80 + (c16 << 4));
            cp16(dst, src);
        }
        CP_COMMIT();
    };

    load_chunk(0, 0);
    for (int cc = 0; cc < nc; cc++) {
        const int cur = cc & 1;
        if (cc + 1 < nc) { load_chunk((cc + 1) & 1, cc + 1); CP_WAIT(1); }
        else             { CP_WAIT(0); }
        __syncthreads();

        const u32 sb = smem_base + cur * STG_BYTES;
        const u32 sa_h = sb + a_off;
        const u32 sa_l = sb + ARR_BYTES   + a_off;
        const u32 sb_h = sb + 2*ARR_BYTES + b_off;

        #pragma unroll
        for (int ks = 0; ks < 2; ks++) {
            const u32 ko = (u32)(ks * 32);
            u32 ah[4][4], al[4][4], bb[2][4];
            #pragma unroll
            for (int mi = 0; mi < 4; mi++) {
                ldsm_x4(sa_h + (u32)(mi * 1280) + ko, ah[mi]);
                ldsm_x4(sa_l + (u32)(mi * 1280) + ko, al[mi]);
            }
            #pragma unroll
            for (int nb = 0; nb < 2; nb++)
                ldsm_x4(sb_h + (u32)(nb * 1280) + ko, bb[nb]);
            #pragma unroll
            for (int mi = 0; mi < 4; mi++)
                #pragma unroll
                for (int ni = 0; ni < 4; ni++) {
                    mma_f16(c[mi][ni], ah[mi], &bb[ni >> 1][(ni & 1) * 2]);
                    mma_f16(c[mi][ni], al[mi], &bb[ni >> 1][(ni & 1) * 2]);
                }
        }
        __syncthreads();
    }

    const int r0 = wm*64 + (lane >> 2);
    const int cc0 = wn*32 + (lane & 3)*2;

    #pragma unroll
    for (int mi = 0; mi < 4; mi++) {
        #pragma unroll
        for (int half = 0; half < 2; half++) {
            const size_t orow = arow + r0 + mi*16 + half*8;
            #pragma unroll
            for (int ni = 0; ni < 4; ni++) {
                const size_t ncol = brow + cc0 + ni*8;
                float v0 = c[mi][ni][half*2+0] + bias[ncol];
                float v1 = c[mi][ni][half*2+1] + bias[ncol+1];
                if (mode == 2) {
                    v0 = fmaxf(v0, 0.f); v1 = fmaxf(v1, 0.f);
                    __half h0,l0,h1,l1;
                    split2h(v0,h0,l0); split2h(v1,h1,l1);
                    __half2 p;
                    p.x=h0; p.y=h1; *(__half2*)(oh + orow*(size_t)Ntot + ncol) = p;
                    p.x=l0; p.y=l1; *(__half2*)(ol + orow*(size_t)Ntot + ncol) = p;
                } else if (mode == 4) {
                    *(__half2*)(oh + orow*(size_t)Ntot + ncol) = __floats2half2_rn(v0, v1);
                } else if (mode == 3) {
                    const float* rp = resid + orow*(size_t)Ntot + ncol;
                    float2 o; o.x = v0 + rp[0]; o.y = v1 + rp[1];
                    *(float2*)(outf + orow*(size_t)Ntot + ncol) = o;
                } else {
                    float2 o; o.x = v0; o.y = v1;
                    *(float2*)(outf + orow*(size_t)Ntot + ncol) = o;
                }
            }
        }
    }
}

// ======================= HMMA attention core =======================
// one CTA = one (batch, head). Q,K,V: 64x48 fp16 in smem (row stride 112 B).
#define ATS 112          // bytes per smem row
#define AARR 7168        // 64*112

__global__ __launch_bounds__(128) void attn_kernel()
{
    __shared__ __align__(16) char sm[3*AARR];
    const u32 smb = smem_u32(sm);

    const int tid = threadIdx.x;
    const int wid = tid >> 5;
    const int lane = tid & 31;
    const int bh = blockIdx.x;
    const int b = bh >> 3;
    const int h = bh & 7;
    const float kScale = 0.14433756729740643f;   // 48^-0.5

    // ---- load q/k/v (64 rows x 288 contiguous bytes) ----
    {
        const __half* src = g_qkv16 + (size_t)(b*TT) * NQKV + h*144;
        #pragma unroll
        for (int i = 0; i < 9; i++) {
            int s = tid + (i << 7);             // 0..1151
            int r = s / 18;
            int j = s - r*18;                    // 0..17
            int arr = j / 6;                     // 0=q 1=k 2=v
            int jj = j - arr*6;
            cp16(smb + arr*AARR + r*ATS + jj*16,
                 src + (size_t)r*NQKV + j*8);
        }
        CP_COMMIT(); CP_WAIT(0);
        __syncthreads();
    }

    const u32 smQ = smb, smK = smb + AARR, smV = smb + 2*AARR;

    // fragment addresses
    const u32 a_addr  = smQ + (u32)((16*wid + (lane & 15)) * ATS + (lane >> 4) * 16);
    const u32 kb_addr = smK + (u32)((((lane & 7) | ((lane >> 1) & 8))) * ATS
                                    + ((lane >> 3) & 1) * 16);
    const int vg = lane >> 3;                    // 0..3
    const u32 vb_addr = smV + (u32)(((vg & 1) * 8 + (lane & 7)) * ATS + (vg >> 1) * 16);

    // ---- S = Q @ K^T (m16 per warp, n64, k48) ----
    float sc[8][4];
    #pragma unroll
    for (int nb = 0; nb < 8; nb++)
        #pragma unroll
        for (int j = 0; j < 4; j++) sc[nb][j] = 0.f;

    {
        u32 aq[3][4];
        #pragma unroll
        for (int ks = 0; ks < 3; ks++) ldsm_x4(a_addr + ks*32, aq[ks]);
        #pragma unroll
        for (int np = 0; np < 4; np++) {        // n-block pair: n0 = 16*np
            #pragma unroll
            for (int ks = 0; ks < 3; ks++) {
                u32 bb[4];
                ldsm_x4(kb_addr + (u32)(np*16*ATS) + ks*32, bb);
                mma_f16(sc[2*np],   aq[ks], &bb[0]);
                mma_f16(sc[2*np+1], aq[ks], &bb[2]);
            }
        }
    }

    // ---- causal mask + softmax (rows: lo = 16w+(lane>>2), hi = +8) ----
    const int r_lo = 16*wid + (lane >> 2);
    const int c0 = (lane & 3) * 2;
    float mlo = -1e30f, mhi = -1e30f;
    #pragma unroll
    for (int nb = 0; nb < 8; nb++) {
        const int cA = nb*8 + c0, cB = cA + 1;
        if (cA > r_lo)     sc[nb][0] = -1e30f;
        if (cB > r_lo)     sc[nb][1] = -1e30f;
        if (cA > r_lo + 8) sc[nb][2] = -1e30f;
        if (cB > r_lo + 8) sc[nb][3] = -1e30f;
        mlo = fmaxf(mlo, fmaxf(sc[nb][0], sc[nb][1]));
        mhi = fmaxf(mhi, fmaxf(sc[nb][2], sc[nb][3]));
    }
    #pragma unroll
    for (int o = 1; o <= 2; o <<= 1) {
        mlo = fmaxf(mlo, __shfl_xor_sync(0xffffffffu, mlo, o));
        mhi = fmaxf(mhi, __shfl_xor_sync(0xffffffffu, mhi, o));
    }
    mlo *= kScale; mhi *= kScale;
    float slo = 0.f, shi = 0.f;
    #pragma unroll
    for (int nb = 0; nb < 8; nb++) {
        sc[nb][0] = __expf(sc[nb][0]*kScale - mlo);
        sc[nb][1] = __expf(sc[nb][1]*kScale - mlo);
        sc[nb][2] = __expf(sc[nb][2]*kScale - mhi);
        sc[nb][3] = __expf(sc[nb][3]*kScale - mhi);
        slo += sc[nb][0] + sc[nb][1];
        shi += sc[nb][2] + sc[nb][3];
    }
    #pragma unroll
    for (int o = 1; o <= 2; o <<= 1) {
        slo += __shfl_xor_sync(0xffffffffu, slo, o);
        shi += __shfl_xor_sync(0xffffffffu, shi, o);
    }
    const float ilo = 1.0f / slo, ihi = 1.0f / shi;
    #pragma unroll
    for (int nb = 0; nb < 8; nb++) {
        sc[nb][0] *= ilo; sc[nb][1] *= ilo;
        sc[nb][2] *= ihi; sc[nb][3] *= ihi;
    }

    // ---- P fragments (A-operand layout) ----
    u32 pf[4][4];
    #pragma unroll
    for (int ks = 0; ks < 4; ks++) {
        const int t0 = 2*ks, t1 = 2*ks + 1;
        pf[ks][0] = h2u(sc[t0][0], sc[t0][1]);
        pf[ks][1] = h2u(sc[t0][2], sc[t0][3]);
        pf[ks][2] = h2u(sc[t1][0], sc[t1][1]);
        pf[ks][3] = h2u(sc[t1][2], sc[t1][3]);
    }

    // ---- O = P @ V (n48, k64), V via trans ldmatrix ----
    float oc[6][4];
    #pragma unroll
    for (int nb = 0; nb < 6; nb++)
        #pragma unroll
        for (int j = 0; j < 4; j++) oc[nb][j] = 0.f;

    #pragma unroll
    for (int ks = 0; ks < 4; ks++) {
        #pragma unroll
        for (int np = 0; np < 3; np++) {        // n0 = 16*np
            u32 vb[4];
            ldsm_x4_t(vb_addr + (u32)(ks*16*ATS) + (u32)(np*32), vb);
            mma_f16(oc[2*np],   pf[ks], &vb[0]);
            mma_f16(oc[2*np+1], pf[ks], &vb[2]);
        }
    }

    // ---- store attn output (fp16 hi/lo split) ----
    #pragma unroll
    for (int nb = 0; nb < 6; nb++) {
        #pragma unroll
        for (int half = 0; half < 2; half++) {
            const int r = r_lo + 8*half;
            const size_t row = (size_t)(b*TT + r);
            const int col = h*HS + nb*8 + c0;
            float v0 = oc[nb][half*2+0], v1 = oc[nb][half*2+1];
            __half h0,l0,h1,l1;
            split2h(v0,h0,l0); split2h(v1,h1,l1);
            __half2 p;
            p.x=h0; p.y=h1; *(__half2*)(g_at_hi + row*DD + col) = p;
            p.x=l0; p.y=l1; *(__half2*)(g_at_lo + row*DD + col) = p;
        }
    }
}

// ======================= host launcher =======================
template <typename T>
static void* sym_addr(T& sym) { void* p = nullptr; cudaGetSymbolAddress(&p, sym); return p; }

extern "C" void kernel_launch(void* const* d_in, const int* in_sizes, int n_in,
                              void* d_out, int out_size) {
    const float* x   = (const float*)d_in[0];
    const float* wq  = (const float*)d_in[1];
    const float* bq  = (const float*)d_in[2];
    const float* wk  = (const float*)d_in[3];
    const float* bk  = (const float*)d_in[4];
    const float* wv  = (const float*)d_in[5];
    const float* bv  = (const float*)d_in[6];
    const float* wo  = (const float*)d_in[7];
    const float* bo  = (const float*)d_in[8];
    const float* w1  = (const float*)d_in[9];
    const float* b1  = (const float*)d_in[10];
    const float* w2  = (const float*)d_in[11];
    const float* b2  = (const float*)d_in[12];
    const float* g1  = (const float*)d_in[13];
    const float* be1 = (const float*)d_in[14];
    const float* g2  = (const float*)d_in[15];
    const float* be2 = (const float*)d_in[16];
    float* out = (float*)d_out;

    const int nb = in_sizes[0] / (TT * DD);
    const int M  = nb * TT;
    const int Mtiles = M / 128;

    float* p_h      = (float*)sym_addr(g_h);
    __half* p_h_hi  = (__half*)sym_addr(g_h_hi);
    __half* p_h_lo  = (__half*)sym_addr(g_h_lo);
    __half* p_qkv16 = (__half*)sym_addr(g_qkv16);
    __half* p_at_hi = (__half*)sym_addr(g_at_hi);
    __half* p_at_lo = (__half*)sym_addr(g_at_lo);
    float* p_s      = (float*)sym_addr(g_s);
    float* p_h2     = (float*)sym_addr(g_h2);
    __half* p_h2_hi = (__half*)sym_addr(g_h2_hi);
    __half* p_h2_lo = (__half*)sym_addr(g_h2_lo);
    __half* p_r_hi  = (__half*)sym_addr(g_r_hi);
    __half* p_r_lo  = (__half*)sym_addr(g_r_lo);
    __half* p_wqkv  = (__half*)sym_addr(g_wqkv);
    __half* p_wot   = (__half*)sym_addr(g_wot);
    __half* p_w1t   = (__half*)sym_addr(g_w1t);
    __half* p_w2t   = (__half*)sym_addr(g_w2t);
    float* p_bqkv   = (float*)sym_addr(g_bqkv);

    cudaFuncSetAttribute(gemm_kernel, cudaFuncAttributeMaxDynamicSharedMemorySize, GSM_TOTAL);

    // 1. weight fp16 convert / transpose
    split_weights_kernel<<<1024, 256>>>(wq, bq, wk, bk, wv, bv, wo, w1, w2);

    // 2. LN1
    ln_kernel<<<M/8, 256>>>(x, nullptr, g1, be1, p_h, p_h_hi, p_h_lo, M);

    // 3. QKV GEMM (fp16 direct output)
    gemm_kernel<<<Mtiles*9, 256, GSM_TOTAL>>>(
        p_h_hi, p_h_lo, p_wqkv, p_bqkv, nullptr,
        nullptr, p_qkv16, nullptr, DD, 9, NQKV, 4);

    // 4. HMMA attention core
    attn_kernel<<<nb*NH, 128>>>();

    // 5. wo GEMM
    gemm_kernel<<<Mtiles*3, 256, GSM_TOTAL>>>(
        p_at_hi, p_at_lo, p_wot, bo, nullptr,
        p_s, nullptr, nullptr, DD, 3, DD, 0);

    // 6. LN2
    ln_kernel<<<M/8, 256>>>(p_h, p_s, g2, be2, p_h2, p_h2_hi, p_h2_lo, M);

    // 7. FF1
    gemm_kernel<<<Mtiles*12, 256, GSM_TOTAL>>>(
        p_h2_hi, p_h2_lo, p_w1t, b1, nullptr,
        nullptr, p_r_hi, p_r_lo, DD, 12, FFD, 2);

    // 8. FF2
    gemm_kernel<<<Mtiles*3, 256, GSM_TOTAL>>>(
        p_r_hi, p_r_lo, p_w2t, b2, p_h2,
        out, nullptr, nullptr, FFD, 3, DD, 3);
}

// round 12
// speedup vs baseline: 8.0374x; 1.5722x over previous
#include <cuda_runtime.h>
#include <cuda_fp16.h>
#include <cstdint>
#include <cstring>

#define TT 64
#define DD 384
#define NH 8
#define HS 48
#define FFD 1536
#define NQKV 1152
#define NBMAX 2048
#define MROWS (NBMAX*TT)

typedef unsigned long long u64;
typedef unsigned int u32;

// ======================= device scratch buffers =======================
__device__ __half g_wqkv[NQKV*DD];
__device__ __half g_wot[DD*DD];
__device__ __half g_w1t[FFD*DD];
__device__ __half g_w2t[DD*FFD];
__device__ float g_bqkv[NQKV];
__device__ float g_h[(size_t)MROWS*DD];
__device__ __half g_h16[(size_t)MROWS*DD];
__device__ __half g_qkv16[(size_t)MROWS*NQKV];
__device__ __half g_at16[(size_t)MROWS*DD];
__device__ float g_s[(size_t)MROWS*DD];
__device__ float g_h2[(size_t)MROWS*DD];
__device__ __half g_h216[(size_t)MROWS*DD];
__device__ __half g_r16[(size_t)MROWS*FFD];

// ======================= helpers =======================
__device__ __forceinline__ u32 h2u(float a, float b) {
    __half2 h = __floats2half2_rn(a, b);
    u32 r; memcpy(&r, &h, 4); return r;
}
__device__ __forceinline__ u32 smem_u32(const void* p) {
    u32 a; asm("{ .reg .u64 t; cvta.to.shared.u64 t, %1; cvt.u32.u64 %0, t; }" : "=r"(a) : "l"(p));
    return a;
}
__device__ __forceinline__ void cp16(u32 dst, const void* src) {
    asm volatile("cp.async.cg.shared.global [%0], [%1], 16;" :: "r"(dst), "l"(src));
}
#define CP_COMMIT()  asm volatile("cp.async.commit_group;" ::: "memory")
#define CP_WAIT(n)   asm volatile("cp.async.wait_group %0;" :: "n"(n) : "memory")

__device__ __forceinline__ void ldsm_x4(u32 addr, u32* r) {
    asm volatile("ldmatrix.sync.aligned.m8n8.x4.shared.b16 {%0,%1,%2,%3}, [%4];"
        : "=r"(r[0]), "=r"(r[1]), "=r"(r[2]), "=r"(r[3]) : "r"(addr));
}
__device__ __forceinline__ void ldsm_x4_t(u32 addr, u32* r) {
    asm volatile("ldmatrix.sync.aligned.m8n8.x4.trans.shared.b16 {%0,%1,%2,%3}, [%4];"
        : "=r"(r[0]), "=r"(r[1]), "=r"(r[2]), "=r"(r[3]) : "r"(addr));
}
__device__ __forceinline__ void mma_f16(float* c, const u32* a, const u32* b) {
    asm volatile("mma.sync.aligned.m16n8k16.row.col.f32.f16.f16.f32 "
        "{%0,%1,%2,%3}, {%4,%5,%6,%7}, {%8,%9}, {%0,%1,%2,%3};"
        : "+f"(c[0]), "+f"(c[1]), "+f"(c[2]), "+f"(c[3])
        : "r"(a[0]), "r"(a[1]), "r"(a[2]), "r"(a[3]), "r"(b[0]), "r"(b[1]));
}

// ======================= weight fp16 convert / transpose =======================
__global__ void split_weights_kernel(
    const float* __restrict__ wq, const float* __restrict__ bq,
    const float* __restrict__ wk, const float* __restrict__ bk,
    const float* __restrict__ wv, const float* __restrict__ bv,
    const float* __restrict__ wo, const float* __restrict__ w1,
    const float* __restrict__ w2)
{
    const int stride = gridDim.x * blockDim.x;
    const int t0 = blockIdx.x * blockDim.x + threadIdx.x;
    for (int i = t0; i < NQKV*DD; i += stride) {
        int n = i / DD, k = i - n*DD;
        int h = n / 144, rm = n - h*144, m = rm / 48, e = rm - m*48;
        const float* src = (m==0) ? wq : ((m==1) ? wk : wv);
        g_wqkv[i] = __float2half_rn(src[((size_t)(h*DD + k))*HS + e]);
    }
    for (int i = t0; i < DD*DD; i += stride) {
        int n = i / DD, k = i - n*DD;
        g_wot[i] = __float2half_rn(wo[(size_t)k*DD + n]);
    }
    for (int i = t0; i < FFD*DD; i += stride) {
        int n = i / DD, k = i - n*DD;
        g_w1t[i] = __float2half_rn(w1[(size_t)k*FFD + n]);
    }
    for (int i = t0; i < DD*FFD; i += stride) {
        int n = i / FFD, k = i - n*FFD;
        g_w2t[i] = __float2half_rn(w2[(size_t)k*DD + n]);
    }
    for (int i = t0; i < NQKV; i += stride) {
        int h = i / 144, rm = i - h*144, m = rm / 48, e = rm - m*48;
        g_bqkv[i] = (m==0 ? bq : (m==1 ? bk : bv))[h*HS + e];
    }
}

// ======================= layernorm (+optional add) + fp16 out =======================
__global__ __launch_bounds__(256) void ln_kernel(
    const float* __restrict__ in1, const float* __restrict__ in2,
    const float* __restrict__ gg, const float* __restrict__ bb,
    float* __restrict__ outf, __half* __restrict__ oh,
    int nrows)
{
    int r = blockIdx.x*8 + (threadIdx.x >> 5);
    int l = threadIdx.x & 31;
    if (r >= nrows) return;
    size_t ro = (size_t)r * DD;
    float v[12]; float s1 = 0.f, s2 = 0.f;
    #pragma unroll
    for (int jt = 0; jt < 3; jt++) {
        int c = jt*128 + 4*l;
        float4 a = *(const float4*)(in1 + ro + c);
        if (in2) {
            float4 b = *(const float4*)(in2 + ro + c);
            a.x += b.x; a.y += b.y; a.z += b.z; a.w += b.w;
        }
        v[4*jt+0]=a.x; v[4*jt+1]=a.y; v[4*jt+2]=a.z; v[4*jt+3]=a.w;
    }
    #pragma unroll
    for (int i = 0; i < 12; i++) { s1 += v[i]; s2 += v[i]*v[i]; }
    #pragma unroll
    for (int o = 16; o > 0; o >>= 1) {
        s1 += __shfl_xor_sync(0xffffffffu, s1, o);
        s2 += __shfl_xor_sync(0xffffffffu, s2, o);
    }
    float mean = s1 * (1.0f/384.0f);
    float var  = s2 * (1.0f/384.0f) - mean*mean;
    float rstd = rsqrtf(var + 1e-5f);
    #pragma unroll
    for (int jt = 0; jt < 3; jt++) {
        int c = jt*128 + 4*l;
        float4 gv = *(const float4*)(gg + c);
        float4 bv = *(const float4*)(bb + c);
        float y0 = (v[4*jt+0]-mean)*rstd*gv.x + bv.x;
        float y1 = (v[4*jt+1]-mean)*rstd*gv.y + bv.y;
        float y2 = (v[4*jt+2]-mean)*rstd*gv.z + bv.z;
        float y3 = (v[4*jt+3]-mean)*rstd*gv.w + bv.w;
        *(float4*)(outf + ro + c) = make_float4(y0, y1, y2, y3);
        *(__half2*)(oh + ro + c)     = __floats2half2_rn(y0, y1);
        *(__half2*)(oh + ro + c + 2) = __floats2half2_rn(y2, y3);
    }
}

// ======================= fp16 GEMM via mma.sync (single product) =======================
// mode 0: outf = D + bias
// mode 2: oh = fp16(relu(D + bias))
// mode 3: outf = D + bias + resid
// mode 4: oh = fp16(D + bias)
#define ARR_BYTES 10240                  // 128 rows * 80 B
#define STG_BYTES (2*ARR_BYTES)          // 20480
#define GSM_TOTAL (2*STG_BYTES)          // 40960

__global__ __launch_bounds__(256, 2) void gemm_kernel(
    const __half* __restrict__ Ah, const __half* __restrict__ Bh,
    const float* __restrict__ bias, const float* __restrict__ resid,
    float* __restrict__ outf, __half* __restrict__ oh,
    int K, int Ntiles, int Ntot, int mode)
{
    extern __shared__ char smem[];
    const u32 smem_base = smem_u32(smem);
    const int tid = threadIdx.x;
    const int wid = tid >> 5;
    const int lane = tid & 31;

    const int mt = blockIdx.x / Ntiles;
    const int nt = blockIdx.x - mt * Ntiles;
    const size_t arow = (size_t)mt * 128;
    const size_t brow = (size_t)nt * 128;

    const __half* Abase = Ah + arow * (size_t)K;
    const __half* Bbase = Bh + brow * (size_t)K;

    const int wm = wid & 1;
    const int wn = wid >> 1;

    const u32 a_off = (u32)((wm*64 + (lane & 15)) * 80 + (lane >> 4) * 16);
    const u32 b_off = (u32)((wn*32 + ((lane & 7) | ((lane >> 1) & 8))) * 80
                            + ((lane >> 3) & 1) * 16);

    float c[4][4][4];
    #pragma unroll
    for (int mi = 0; mi < 4; mi++)
        #pragma unroll
        for (int ni = 0; ni < 4; ni++)
            #pragma unroll
            for (int j = 0; j < 4; j++) c[mi][ni][j] = 0.f;

    const int nc = K >> 5;

    auto load_chunk = [&](int stage, int cc) {
        const u32 sb = smem_base + stage * STG_BYTES;
        const int c0 = cc << 5;
        #pragma unroll
        for (int i = 0; i < 4; i++) {
            int s = tid + (i << 8);
            int arr = s >> 9;              // 0..1
            int within = s & 511;
            int r   = within >> 2;
            int c16 = within & 3;
            const __half* bp = (arr == 0) ? Abase : Bbase;
            const void* src = bp + (size_t)r * K + c0 + (c16 << 3);
            u32 dst = sb + arr * ARR_BYTES + (u32)(r * 80 + (c16 << 4));
            cp16(dst, src);
        }
        CP_COMMIT();
    };

    load_chunk(0, 0);
    for (int cc = 0; cc < nc; cc++) {
        const int cur = cc & 1;
        if (cc + 1 < nc) { load_chunk((cc + 1) & 1, cc + 1); CP_WAIT(1); }
        else             { CP_WAIT(0); }
        __syncthreads();

        const u32 sb = smem_base + cur * STG_BYTES;
        const u32 sa = sb + a_off;
        const u32 sbh = sb + ARR_BYTES + b_off;

        #pragma unroll
        for (int ks = 0; ks < 2; ks++) {
            const u32 ko = (u32)(ks * 32);
            u32 ah[4][4], bb[2][4];
            #pragma unroll
            for (int mi = 0; mi < 4; mi++)
                ldsm_x4(sa + (u32)(mi * 1280) + ko, ah[mi]);
            #pragma unroll
            for (int nb = 0; nb < 2; nb++)
                ldsm_x4(sbh + (u32)(nb * 1280) + ko, bb[nb]);
            #pragma unroll
            for (int mi = 0; mi < 4; mi++)
                #pragma unroll
                for (int ni = 0; ni < 4; ni++)
                    mma_f16(c[mi][ni], ah[mi], &bb[ni >> 1][(ni & 1) * 2]);
        }
        __syncthreads();
    }

    const int r0 = wm*64 + (lane >> 2);
    const int cc0 = wn*32 + (lane & 3)*2;

    #pragma unroll
    for (int mi = 0; mi < 4; mi++) {
        #pragma unroll
        for (int half = 0; half < 2; half++) {
            const size_t orow = arow + r0 + mi*16 + half*8;
            #pragma unroll
            for (int ni = 0; ni < 4; ni++) {
                const size_t ncol = brow + cc0 + ni*8;
                float v0 = c[mi][ni][half*2+0] + bias[ncol];
                float v1 = c[mi][ni][half*2+1] + bias[ncol+1];
                if (mode == 2) {
                    v0 = fmaxf(v0, 0.f); v1 = fmaxf(v1, 0.f);
                    *(__half2*)(oh + orow*(size_t)Ntot + ncol) = __floats2half2_rn(v0, v1);
                } else if (mode == 4) {
                    *(__half2*)(oh + orow*(size_t)Ntot + ncol) = __floats2half2_rn(v0, v1);
                } else if (mode == 3) {
                    const float* rp = resid + orow*(size_t)Ntot + ncol;
                    float2 o; o.x = v0 + rp[0]; o.y = v1 + rp[1];
                    *(float2*)(outf + orow*(size_t)Ntot + ncol) = o;
                } else {
                    float2 o; o.x = v0; o.y = v1;
                    *(float2*)(outf + orow*(size_t)Ntot + ncol) = o;
                }
            }
        }
    }
}

// ======================= HMMA attention core =======================
// one CTA = one (batch, head). Q,K,V: 64x48 fp16 in smem (row stride 112 B).
#define ATS 112
#define AARR 7168

__global__ __launch_bounds__(128) void attn_kernel()
{
    __shared__ __align__(16) char sm[3*AARR];
    const u32 smb = smem_u32(sm);

    const int tid = threadIdx.x;
    const int wid = tid >> 5;
    const int lane = tid & 31;
    const int bh = blockIdx.x;
    const int b = bh >> 3;
    const int h = bh & 7;
    const float kScale = 0.14433756729740643f;   // 48^-0.5

    // ---- load q/k/v ----
    {
        const __half* src = g_qkv16 + (size_t)(b*TT) * NQKV + h*144;
        #pragma unroll
        for (int i = 0; i < 9; i++) {
            int s = tid + (i << 7);
            int r = s / 18;
            int j = s - r*18;
            int arr = j / 6;
            int jj = j - arr*6;
            cp16(smb + arr*AARR + r*ATS + jj*16,
                 src + (size_t)r*NQKV + j*8);
        }
        CP_COMMIT(); CP_WAIT(0);
        __syncthreads();
    }

    const u32 smQ = smb, smK = smb + AARR, smV = smb + 2*AARR;

    const u32 a_addr  = smQ + (u32)((16*wid + (lane & 15)) * ATS + (lane >> 4) * 16);
    const u32 kb_addr = smK + (u32)((((lane & 7) | ((lane >> 1) & 8))) * ATS
                                    + ((lane >> 3) & 1) * 16);
    const int vg = lane >> 3;
    const u32 vb_addr = smV + (u32)(((vg & 1) * 8 + (lane & 7)) * ATS + (vg >> 1) * 16);

    // ---- S = Q @ K^T ----
    float sc[8][4];
    #pragma unroll
    for (int nb = 0; nb < 8; nb++)
        #pragma unroll
        for (int j = 0; j < 4; j++) sc[nb][j] = 0.f;

    {
        u32 aq[3][4];
        #pragma unroll
        for (int ks = 0; ks < 3; ks++) ldsm_x4(a_addr + ks*32, aq[ks]);
        #pragma unroll
        for (int np = 0; np < 4; np++) {
            #pragma unroll
            for (int ks = 0; ks < 3; ks++) {
                u32 bb[4];
                ldsm_x4(kb_addr + (u32)(np*16*ATS) + ks*32, bb);
                mma_f16(sc[2*np],   aq[ks], &bb[0]);
                mma_f16(sc[2*np+1], aq[ks], &bb[2]);
            }
        }
    }

    // ---- causal mask + softmax ----
    const int r_lo = 16*wid + (lane >> 2);
    const int c0 = (lane & 3) * 2;
    float mlo = -1e30f, mhi = -1e30f;
    #pragma unroll
    for (int nb = 0; nb < 8; nb++) {
        const int cA = nb*8 + c0, cB = cA + 1;
        if (cA > r_lo)     sc[nb][0] = -1e30f;
        if (cB > r_lo)     sc[nb][1] = -1e30f;
        if (cA > r_lo + 8) sc[nb][2] = -1e30f;
        if (cB > r_lo + 8) sc[nb][3] = -1e30f;
        mlo = fmaxf(mlo, fmaxf(sc[nb][0], sc[nb][1]));
        mhi = fmaxf(mhi, fmaxf(sc[nb][2], sc[nb][3]));
    }
    #pragma unroll
    for (int o = 1; o <= 2; o <<= 1) {
        mlo = fmaxf(mlo, __shfl_xor_sync(0xffffffffu, mlo, o));
        mhi = fmaxf(mhi, __shfl_xor_sync(0xffffffffu, mhi, o));
    }
    mlo *= kScale; mhi *= kScale;
    float slo = 0.f, shi = 0.f;
    #pragma unroll
    for (int nb = 0; nb < 8; nb++) {
        sc[nb][0] = __expf(sc[nb][0]*kScale - mlo);
        sc[nb][1] = __expf(sc[nb][1]*kScale - mlo);
        sc[nb][2] = __expf(sc[nb][2]*kScale - mhi);
        sc[nb][3] = __expf(sc[nb][3]*kScale - mhi);
        slo += sc[nb][0] + sc[nb][1];
        shi += sc[nb][2] + sc[nb][3];
    }
    #pragma unroll
    for (int o = 1; o <= 2; o <<= 1) {
        slo += __shfl_xor_sync(0xffffffffu, slo, o);
        shi += __shfl_xor_sync(0xffffffffu, shi, o);
    }
    const float ilo = 1.0f / slo, ihi = 1.0f / shi;
    #pragma unroll
    for (int nb = 0; nb < 8; nb++) {
        sc[nb][0] *= ilo; sc[nb][1] *= ilo;
        sc[nb][2] *= ihi; sc[nb][3] *= ihi;
    }

    // ---- P fragments ----
    u32 pf[4][4];
    #pragma unroll
    for (int ks = 0; ks < 4; ks++) {
        const int t0 = 2*ks, t1 = 2*ks + 1;
        pf[ks][0] = h2u(sc[t0][0], sc[t0][1]);
        pf[ks][1] = h2u(sc[t0][2], sc[t0][3]);
        pf[ks][2] = h2u(sc[t1][0], sc[t1][1]);
        pf[ks][3] = h2u(sc[t1][2], sc[t1][3]);
    }

    // ---- O = P @ V ----
    float oc[6][4];
    #pragma unroll
    for (int nb = 0; nb < 6; nb++)
        #pragma unroll
        for (int j = 0; j < 4; j++) oc[nb][j] = 0.f;

    #pragma unroll
    for (int ks = 0; ks < 4; ks++) {
        #pragma unroll
        for (int np = 0; np < 3; np++) {
            u32 vb[4];
            ldsm_x4_t(vb_addr + (u32)(ks*16*ATS) + (u32)(np*32), vb);
            mma_f16(oc[2*np],   pf[ks], &vb[0]);
            mma_f16(oc[2*np+1], pf[ks], &vb[2]);
        }
    }

    // ---- store attn output (fp16) ----
    #pragma unroll
    for (int nb = 0; nb < 6; nb++) {
        #pragma unroll
        for (int half = 0; half < 2; half++) {
            const int r = r_lo + 8*half;
            const size_t row = (size_t)(b*TT + r);
            const int col = h*HS + nb*8 + c0;
            *(__half2*)(g_at16 + row*DD + col) =
                __floats2half2_rn(oc[nb][half*2+0], oc[nb][half*2+1]);
        }
    }
}

// ======================= host launcher =======================
template <typename T>
static void* sym_addr(T& sym) { void* p = nullptr; cudaGetSymbolAddress(&p, sym); return p; }

extern "C" void kernel_launch(void* const* d_in, const int* in_sizes, int n_in,
                              void* d_out, int out_size) {
    const float* x   = (const float*)d_in[0];
    const float* wq  = (const float*)d_in[1];
    const float* bq  = (const float*)d_in[2];
    const float* wk  = (const float*)d_in[3];
    const float* bk  = (const float*)d_in[4];
    const float* wv  = (const float*)d_in[5];
    const float* bv  = (const float*)d_in[6];
    const float* wo  = (const float*)d_in[7];
    const float* bo  = (const float*)d_in[8];
    const float* w1  = (const float*)d_in[9];
    const float* b1  = (const float*)d_in[10];
    const float* w2  = (const float*)d_in[11];
    const float* b2  = (const float*)d_in[12];
    const float* g1  = (const float*)d_in[13];
    const float* be1 = (const float*)d_in[14];
    const float* g2  = (const float*)d_in[15];
    const float* be2 = (const float*)d_in[16];
    float* out = (float*)d_out;

    const int nb = in_sizes[0] / (TT * DD);
    const int M  = nb * TT;
    const int Mtiles = M / 128;

    float* p_h      = (float*)sym_addr(g_h);
    __half* p_h16   = (__half*)sym_addr(g_h16);
    __half* p_qkv16 = (__half*)sym_addr(g_qkv16);
    __half* p_at16  = (__half*)sym_addr(g_at16);
    float* p_s      = (float*)sym_addr(g_s);
    float* p_h2     = (float*)sym_addr(g_h2);
    __half* p_h216  = (__half*)sym_addr(g_h216);
    __half* p_r16   = (__half*)sym_addr(g_r16);
    __half* p_wqkv  = (__half*)sym_addr(g_wqkv);
    __half* p_wot   = (__half*)sym_addr(g_wot);
    __half* p_w1t   = (__half*)sym_addr(g_w1t);
    __half* p_w2t   = (__half*)sym_addr(g_w2t);
    float* p_bqkv   = (float*)sym_addr(g_bqkv);

    cudaFuncSetAttribute(gemm_kernel, cudaFuncAttributeMaxDynamicSharedMemorySize, GSM_TOTAL);

    // 1. weight fp16 convert / transpose
    split_weights_kernel<<<1024, 256>>>(wq, bq, wk, bk, wv, bv, wo, w1, w2);

    // 2. LN1
    ln_kernel<<<M/8, 256>>>(x, nullptr, g1, be1, p_h, p_h16, M);

    // 3. QKV GEMM (fp16 direct output)
    gemm_kernel<<<Mtiles*9, 256, GSM_TOTAL>>>(
        p_h16, p_wqkv, p_bqkv, nullptr,
        nullptr, p_qkv16, DD, 9, NQKV, 4);

    // 4. HMMA attention core
    attn_kernel<<<nb*NH, 128>>>();

    // 5. wo GEMM
    gemm_kernel<<<Mtiles*3, 256, GSM_TOTAL>>>(
        p_at16, p_wot, bo, nullptr,
        p_s, nullptr, DD, 3, DD, 0);

    // 6. LN2
    ln_kernel<<<M/8, 256>>>(p_h, p_s, g2, be2, p_h2, p_h216, M);

    // 7. FF1
    gemm_kernel<<<Mtiles*12, 256, GSM_TOTAL>>>(
        p_h216, p_w1t, b1, nullptr,
        nullptr, p_r16, DD, 12, FFD, 2);

    // 8. FF2
    gemm_kernel<<<Mtiles*3, 256, GSM_TOTAL>>>(
        p_r16, p_w2t, b2, p_h2,
        out, nullptr, FFD, 3, DD, 3);
}

// round 13
// speedup vs baseline: 9.2112x; 1.1460x over previous
#include <cuda_runtime.h>
#include <cuda_fp16.h>
#include <cstdint>
#include <cstring>

#define TT 64
#define DD 384
#define NH 8
#define HS 48
#define FFD 1536
#define NQKV 1152
#define NBMAX 2048
#define MROWS (NBMAX*TT)

typedef unsigned long long u64;
typedef unsigned int u32;

// ======================= device scratch buffers =======================
__device__ __half g_wqkv[NQKV*DD];
__device__ __half g_wot[DD*DD];
__device__ __half g_w1t[FFD*DD];
__device__ __half g_w2t[DD*FFD];
__device__ float g_bqkv[NQKV];
__device__ float g_h[(size_t)MROWS*DD];
__device__ __half g_h16[(size_t)MROWS*DD];
__device__ __half g_qkv16[(size_t)MROWS*NQKV];
__device__ __half g_at16[(size_t)MROWS*DD];
__device__ float g_hs[(size_t)MROWS*DD];     // h + attn (wo epilogue residual add)
__device__ float g_h2[(size_t)MROWS*DD];
__device__ __half g_h216[(size_t)MROWS*DD];
__device__ __half g_r16[(size_t)MROWS*FFD];

// ======================= helpers =======================
__device__ __forceinline__ u32 h2u(float a, float b) {
    __half2 h = __floats2half2_rn(a, b);
    u32 r; memcpy(&r, &h, 4); return r;
}
__device__ __forceinline__ u32 smem_u32(const void* p) {
    u32 a; asm("{ .reg .u64 t; cvta.to.shared.u64 t, %1; cvt.u32.u64 %0, t; }" : "=r"(a) : "l"(p));
    return a;
}
__device__ __forceinline__ void cp16(u32 dst, const void* src) {
    asm volatile("cp.async.cg.shared.global [%0], [%1], 16;" :: "r"(dst), "l"(src));
}
#define CP_COMMIT()  asm volatile("cp.async.commit_group;" ::: "memory")
#define CP_WAIT(n)   asm volatile("cp.async.wait_group %0;" :: "n"(n) : "memory")

__device__ __forceinline__ void ldsm_x4(u32 addr, u32* r) {
    asm volatile("ldmatrix.sync.aligned.m8n8.x4.shared.b16 {%0,%1,%2,%3}, [%4];"
        : "=r"(r[0]), "=r"(r[1]), "=r"(r[2]), "=r"(r[3]) : "r"(addr));
}
__device__ __forceinline__ void ldsm_x4_t(u32 addr, u32* r) {
    asm volatile("ldmatrix.sync.aligned.m8n8.x4.trans.shared.b16 {%0,%1,%2,%3}, [%4];"
        : "=r"(r[0]), "=r"(r[1]), "=r"(r[2]), "=r"(r[3]) : "r"(addr));
}
__device__ __forceinline__ void mma_f16(float* c, const u32* a, const u32* b) {
    asm volatile("mma.sync.aligned.m16n8k16.row.col.f32.f16.f16.f32 "
        "{%0,%1,%2,%3}, {%4,%5,%6,%7}, {%8,%9}, {%0,%1,%2,%3};"
        : "+f"(c[0]), "+f"(c[1]), "+f"(c[2]), "+f"(c[3])
        : "r"(a[0]), "r"(a[1]), "r"(a[2]), "r"(a[3]), "r"(b[0]), "r"(b[1]));
}

// ======================= weight fp16 convert / transpose =======================
__global__ void split_weights_kernel(
    const float* __restrict__ wq, const float* __restrict__ bq,
    const float* __restrict__ wk, const float* __restrict__ bk,
    const float* __restrict__ wv, const float* __restrict__ bv,
    const float* __restrict__ wo, const float* __restrict__ w1,
    const float* __restrict__ w2)
{
    const int stride = gridDim.x * blockDim.x;
    const int t0 = blockIdx.x * blockDim.x + threadIdx.x;
    for (int i = t0; i < NQKV*DD; i += stride) {
        int n = i / DD, k = i - n*DD;
        int h = n / 144, rm = n - h*144, m = rm / 48, e = rm - m*48;
        const float* src = (m==0) ? wq : ((m==1) ? wk : wv);
        g_wqkv[i] = __float2half_rn(src[((size_t)(h*DD + k))*HS + e]);
    }
    for (int i = t0; i < DD*DD; i += stride) {
        int n = i / DD, k = i - n*DD;
        g_wot[i] = __float2half_rn(wo[(size_t)k*DD + n]);
    }
    for (int i = t0; i < FFD*DD; i += stride) {
        int n = i / DD, k = i - n*DD;
        g_w1t[i] = __float2half_rn(w1[(size_t)k*FFD + n]);
    }
    for (int i = t0; i < DD*FFD; i += stride) {
        int n = i / FFD, k = i - n*FFD;
        g_w2t[i] = __float2half_rn(w2[(size_t)k*DD + n]);
    }
    for (int i = t0; i < NQKV; i += stride) {
        int h = i / 144, rm = i - h*144, m = rm / 48, e = rm - m*48;
        g_bqkv[i] = (m==0 ? bq : (m==1 ? bk : bv))[h*HS + e];
    }
}

// ======================= layernorm + fp16 out =======================
__global__ __launch_bounds__(256) void ln_kernel(
    const float* __restrict__ in1,
    const float* __restrict__ gg, const float* __restrict__ bb,
    float* __restrict__ outf, __half* __restrict__ oh,
    int nrows)
{
    int r = blockIdx.x*8 + (threadIdx.x >> 5);
    int l = threadIdx.x & 31;
    if (r >= nrows) return;
    size_t ro = (size_t)r * DD;
    float v[12]; float s1 = 0.f, s2 = 0.f;
    #pragma unroll
    for (int jt = 0; jt < 3; jt++) {
        int c = jt*128 + 4*l;
        float4 a = *(const float4*)(in1 + ro + c);
        v[4*jt+0]=a.x; v[4*jt+1]=a.y; v[4*jt+2]=a.z; v[4*jt+3]=a.w;
    }
    #pragma unroll
    for (int i = 0; i < 12; i++) { s1 += v[i]; s2 += v[i]*v[i]; }
    #pragma unroll
    for (int o = 16; o > 0; o >>= 1) {
        s1 += __shfl_xor_sync(0xffffffffu, s1, o);
        s2 += __shfl_xor_sync(0xffffffffu, s2, o);
    }
    float mean = s1 * (1.0f/384.0f);
    float var  = s2 * (1.0f/384.0f) - mean*mean;
    float rstd = rsqrtf(var + 1e-5f);
    #pragma unroll
    for (int jt = 0; jt < 3; jt++) {
        int c = jt*128 + 4*l;
        float4 gv = *(const float4*)(gg + c);
        float4 bv = *(const float4*)(bb + c);
        float y0 = (v[4*jt+0]-mean)*rstd*gv.x + bv.x;
        float y1 = (v[4*jt+1]-mean)*rstd*gv.y + bv.y;
        float y2 = (v[4*jt+2]-mean)*rstd*gv.z + bv.z;
        float y3 = (v[4*jt+3]-mean)*rstd*gv.w + bv.w;
        if (outf) *(float4*)(outf + ro + c) = make_float4(y0, y1, y2, y3);
        *(__half2*)(oh + ro + c)     = __floats2half2_rn(y0, y1);
        *(__half2*)(oh + ro + c + 2) = __floats2half2_rn(y2, y3);
    }
}

// ======================= fp16 GEMM via mma.sync (K-chunk 64) =======================
// mode 0: outf = D + bias
// mode 2: oh = fp16(relu(D + bias))
// mode 3: outf = D + bias + resid
// mode 4: oh = fp16(D + bias)
#define ARR_BYTES 18432                  // 128 rows * 144 B (64 fp16 cols + 16B pad)
#define STG_BYTES (2*ARR_BYTES)          // 36864
#define GSM_TOTAL (2*STG_BYTES)          // 73728

__global__ __launch_bounds__(256, 2) void gemm_kernel(
    const __half* __restrict__ Ah, const __half* __restrict__ Bh,
    const float* __restrict__ bias, const float* __restrict__ resid,
    float* __restrict__ outf, __half* __restrict__ oh,
    int K, int Ntiles, int Ntot, int mode)
{
    extern __shared__ char smem[];
    const u32 smem_base = smem_u32(smem);
    const int tid = threadIdx.x;
    const int wid = tid >> 5;
    const int lane = tid & 31;

    const int mt = blockIdx.x / Ntiles;
    const int nt = blockIdx.x - mt * Ntiles;
    const size_t arow = (size_t)mt * 128;
    const size_t brow = (size_t)nt * 128;

    const __half* Abase = Ah + arow * (size_t)K;
    const __half* Bbase = Bh + brow * (size_t)K;

    const int wm = wid & 1;
    const int wn = wid >> 1;

    const u32 a_off = (u32)((wm*64 + (lane & 15)) * 144 + (lane >> 4) * 16);
    const u32 b_off = (u32)((wn*32 + ((lane & 7) | ((lane >> 1) & 8))) * 144
                            + ((lane >> 3) & 1) * 16);

    float c[4][4][4];
    #pragma unroll
    for (int mi = 0; mi < 4; mi++)
        #pragma unroll
        for (int ni = 0; ni < 4; ni++)
            #pragma unroll
            for (int j = 0; j < 4; j++) c[mi][ni][j] = 0.f;

    const int nc = K >> 6;   // K/64 chunks

    auto load_chunk = [&](int stage, int cc) {
        const u32 sb = smem_base + stage * STG_BYTES;
        const int c0 = cc << 6;
        #pragma unroll
        for (int i = 0; i < 8; i++) {
            int s = tid + (i << 8);
            int arr = s >> 10;             // 0..1
            int within = s & 1023;
            int r   = within >> 3;
            int c16 = within & 7;
            const __half* bp = (arr == 0) ? Abase : Bbase;
            const void* src = bp + (size_t)r * K + c0 + (c16 << 3);
            u32 dst = sb + arr * ARR_BYTES + (u32)(r * 144 + (c16 << 4));
            cp16(dst, src);
        }
        CP_COMMIT();
    };

    load_chunk(0, 0);
    for (int cc = 0; cc < nc; cc++) {
        const int cur = cc & 1;
        if (cc + 1 < nc) { load_chunk((cc + 1) & 1, cc + 1); CP_WAIT(1); }
        else             { CP_WAIT(0); }
        __syncthreads();

        const u32 sb = smem_base + cur * STG_BYTES;
        const u32 sa = sb + a_off;
        const u32 sbh = sb + ARR_BYTES + b_off;

        #pragma unroll
        for (int ks = 0; ks < 4; ks++) {
            const u32 ko = (u32)(ks * 32);     // 16 cols * 2B
            u32 ah[4][4], bb[2][4];
            #pragma unroll
            for (int mi = 0; mi < 4; mi++)
                ldsm_x4(sa + (u32)(mi * 2304) + ko, ah[mi]);
            #pragma unroll
            for (int nb = 0; nb < 2; nb++)
                ldsm_x4(sbh + (u32)(nb * 2304) + ko, bb[nb]);
            #pragma unroll
            for (int mi = 0; mi < 4; mi++)
                #pragma unroll
                for (int ni = 0; ni < 4; ni++)
                    mma_f16(c[mi][ni], ah[mi], &bb[ni >> 1][(ni & 1) * 2]);
        }
        __syncthreads();
    }

    const int r0 = wm*64 + (lane >> 2);
    const int cc0 = wn*32 + (lane & 3)*2;

    #pragma unroll
    for (int mi = 0; mi < 4; mi++) {
        #pragma unroll
        for (int half = 0; half < 2; half++) {
            const size_t orow = arow + r0 + mi*16 + half*8;
            #pragma unroll
            for (int ni = 0; ni < 4; ni++) {
                const size_t ncol = brow + cc0 + ni*8;
                float v0 = c[mi][ni][half*2+0] + bias[ncol];
                float v1 = c[mi][ni][half*2+1] + bias[ncol+1];
                if (mode == 2) {
                    v0 = fmaxf(v0, 0.f); v1 = fmaxf(v1, 0.f);
                    *(__half2*)(oh + orow*(size_t)Ntot + ncol) = __floats2half2_rn(v0, v1);
                } else if (mode == 4) {
                    *(__half2*)(oh + orow*(size_t)Ntot + ncol) = __floats2half2_rn(v0, v1);
                } else if (mode == 3) {
                    const float* rp = resid + orow*(size_t)Ntot + ncol;
                    float2 o; o.x = v0 + rp[0]; o.y = v1 + rp[1];
                    *(float2*)(outf + orow*(size_t)Ntot + ncol) = o;
                } else {
                    float2 o; o.x = v0; o.y = v1;
                    *(float2*)(outf + orow*(size_t)Ntot + ncol) = o;
                }
            }
        }
    }
}

// ======================= HMMA attention core =======================
#define ATS 112
#define AARR 7168

__global__ __launch_bounds__(128) void attn_kernel()
{
    __shared__ __align__(16) char sm[3*AARR];
    const u32 smb = smem_u32(sm);

    const int tid = threadIdx.x;
    const int wid = tid >> 5;
    const int lane = tid & 31;
    const int bh = blockIdx.x;
    const int b = bh >> 3;
    const int h = bh & 7;
    const float kScale = 0.14433756729740643f;   // 48^-0.5

    {
        const __half* src = g_qkv16 + (size_t)(b*TT) * NQKV + h*144;
        #pragma unroll
        for (int i = 0; i < 9; i++) {
            int s = tid + (i << 7);
            int r = s / 18;
            int j = s - r*18;
            int arr = j / 6;
            int jj = j - arr*6;
            cp16(smb + arr*AARR + r*ATS + jj*16,
                 src + (size_t)r*NQKV + j*8);
        }
        CP_COMMIT(); CP_WAIT(0);
        __syncthreads();
    }

    const u32 smQ = smb, smK = smb + AARR, smV = smb + 2*AARR;

    const u32 a_addr  = smQ + (u32)((16*wid + (lane & 15)) * ATS + (lane >> 4) * 16);
    const u32 kb_addr = smK + (u32)((((lane & 7) | ((lane >> 1) & 8))) * ATS
                                    + ((lane >> 3) & 1) * 16);
    const int vg = lane >> 3;
    const u32 vb_addr = smV + (u32)(((vg & 1) * 8 + (lane & 7)) * ATS + (vg >> 1) * 16);

    float sc[8][4];
    #pragma unroll
    for (int nb = 0; nb < 8; nb++)
        #pragma unroll
        for (int j = 0; j < 4; j++) sc[nb][j] = 0.f;

    {
        u32 aq[3][4];
        #pragma unroll
        for (int ks = 0; ks < 3; ks++) ldsm_x4(a_addr + ks*32, aq[ks]);
        #pragma unroll
        for (int np = 0; np < 4; np++) {
            #pragma unroll
            for (int ks = 0; ks < 3; ks++) {
                u32 bb[4];
                ldsm_x4(kb_addr + (u32)(np*16*ATS) + ks*32, bb);
                mma_f16(sc[2*np],   aq[ks], &bb[0]);
                mma_f16(sc[2*np+1], aq[ks], &bb[2]);
            }
        }
    }

    const int r_lo = 16*wid + (lane >> 2);
    const int c0 = (lane & 3) * 2;
    float mlo = -1e30f, mhi = -1e30f;
    #pragma unroll
    for (int nb = 0; nb < 8; nb++) {
        const int cA = nb*8 + c0, cB = cA + 1;
        if (cA > r_lo)     sc[nb][0] = -1e30f;
        if (cB > r_lo)     sc[nb][1] = -1e30f;
        if (cA > r_lo + 8) sc[nb][2] = -1e30f;
        if (cB > r_lo + 8) sc[nb][3] = -1e30f;
        mlo = fmaxf(mlo, fmaxf(sc[nb][0], sc[nb][1]));
        mhi = fmaxf(mhi, fmaxf(sc[nb][2], sc[nb][3]));
    }
    #pragma unroll
    for (int o = 1; o <= 2; o <<= 1) {
        mlo = fmaxf(mlo, __shfl_xor_sync(0xffffffffu, mlo, o));
        mhi = fmaxf(mhi, __shfl_xor_sync(0xffffffffu, mhi, o));
    }
    mlo *= kScale; mhi *= kScale;
    float slo = 0.f, shi = 0.f;
    #pragma unroll
    for (int nb = 0; nb < 8; nb++) {
        sc[nb][0] = __expf(sc[nb][0]*kScale - mlo);
        sc[nb][1] = __expf(sc[nb][1]*kScale - mlo);
        sc[nb][2] = __expf(sc[nb][2]*kScale - mhi);
        sc[nb][3] = __expf(sc[nb][3]*kScale - mhi);
        slo += sc[nb][0] + sc[nb][1];
        shi += sc[nb][2] + sc[nb][3];
    }
    #pragma unroll
    for (int o = 1; o <= 2; o <<= 1) {
        slo += __shfl_xor_sync(0xffffffffu, slo, o);
        shi += __shfl_xor_sync(0xffffffffu, shi, o);
    }
    const float ilo = 1.0f / slo, ihi = 1.0f / shi;
    #pragma unroll
    for (int nb = 0; nb < 8; nb++) {
        sc[nb][0] *= ilo; sc[nb][1] *= ilo;
        sc[nb][2] *= ihi; sc[nb][3] *= ihi;
    }

    u32 pf[4][4];
    #pragma unroll
    for (int ks = 0; ks < 4; ks++) {
        const int t0 = 2*ks, t1 = 2*ks + 1;
        pf[ks][0] = h2u(sc[t0][0], sc[t0][1]);
        pf[ks][1] = h2u(sc[t0][2], sc[t0][3]);
        pf[ks][2] = h2u(sc[t1][0], sc[t1][1]);
        pf[ks][3] = h2u(sc[t1][2], sc[t1][3]);
    }

    float oc[6][4];
    #pragma unroll
    for (int nb = 0; nb < 6; nb++)
        #pragma unroll
        for (int j = 0; j < 4; j++) oc[nb][j] = 0.f;

    #pragma unroll
    for (int ks = 0; ks < 4; ks++) {
        #pragma unroll
        for (int np = 0; np < 3; np++) {
            u32 vb[4];
            ldsm_x4_t(vb_addr + (u32)(ks*16*ATS) + (u32)(np*32), vb);
            mma_f16(oc[2*np],   pf[ks], &vb[0]);
            mma_f16(oc[2*np+1], pf[ks], &vb[2]);
        }
    }

    #pragma unroll
    for (int nb = 0; nb < 6; nb++) {
        #pragma unroll
        for (int half = 0; half < 2; half++) {
            const int r = r_lo + 8*half;
            const size_t row = (size_t)(b*TT + r);
            const int col = h*HS + nb*8 + c0;
            *(__half2*)(g_at16 + row*DD + col) =
                __floats2half2_rn(oc[nb][half*2+0], oc[nb][half*2+1]);
        }
    }
}

// ======================= host launcher =======================
template <typename T>
static void* sym_addr(T& sym) { void* p = nullptr; cudaGetSymbolAddress(&p, sym); return p; }

extern "C" void kernel_launch(void* const* d_in, const int* in_sizes, int n_in,
                              void* d_out, int out_size) {
    const float* x   = (const float*)d_in[0];
    const float* wq  = (const float*)d_in[1];
    const float* bq  = (const float*)d_in[2];
    const float* wk  = (const float*)d_in[3];
    const float* bk  = (const float*)d_in[4];
    const float* wv  = (const float*)d_in[5];
    const float* bv  = (const float*)d_in[6];
    const float* wo  = (const float*)d_in[7];
    const float* bo  = (const float*)d_in[8];
    const float* w1  = (const float*)d_in[9];
    const float* b1  = (const float*)d_in[10];
    const float* w2  = (const float*)d_in[11];
    const float* b2  = (const float*)d_in[12];
    const float* g1  = (const float*)d_in[13];
    const float* be1 = (const float*)d_in[14];
    const float* g2  = (const float*)d_in[15];
    const float* be2 = (const float*)d_in[16];
    float* out = (float*)d_out;

    const int nb = in_sizes[0] / (TT * DD);
    const int M  = nb * TT;
    const int Mtiles = M / 128;

    float* p_h      = (float*)sym_addr(g_h);
    __half* p_h16   = (__half*)sym_addr(g_h16);
    __half* p_qkv16 = (__half*)sym_addr(g_qkv16);
    __half* p_at16  = (__half*)sym_addr(g_at16);
    float* p_hs     = (float*)sym_addr(g_hs);
    float* p_h2     = (float*)sym_addr(g_h2);
    __half* p_h216  = (__half*)sym_addr(g_h216);
    __half* p_r16   = (__half*)sym_addr(g_r16);
    __half* p_wqkv  = (__half*)sym_addr(g_wqkv);
    __half* p_wot   = (__half*)sym_addr(g_wot);
    __half* p_w1t   = (__half*)sym_addr(g_w1t);
    __half* p_w2t   = (__half*)sym_addr(g_w2t);
    float* p_bqkv   = (float*)sym_addr(g_bqkv);

    cudaFuncSetAttribute(gemm_kernel, cudaFuncAttributeMaxDynamicSharedMemorySize, GSM_TOTAL);

    // 1. weight fp16 convert / transpose
    split_weights_kernel<<<1024, 256>>>(wq, bq, wk, bk, wv, bv, wo, w1, w2);

    // 2. LN1: h = ln(x) (fp32 for residual, fp16 for GEMM)
    ln_kernel<<<M/8, 256>>>(x, g1, be1, p_h, p_h16, M);

    // 3. QKV GEMM (fp16 direct output)
    gemm_kernel<<<Mtiles*9, 256, GSM_TOTAL>>>(
        p_h16, p_wqkv, p_bqkv, nullptr,
        nullptr, p_qkv16, DD, 9, NQKV, 4);

    // 4. HMMA attention core
    attn_kernel<<<nb*NH, 128>>>();

    // 5. wo GEMM with fused attention residual: hs = at @ wo + bo + h
    gemm_kernel<<<Mtiles*3, 256, GSM_TOTAL>>>(
        p_at16, p_wot, bo, p_h,
        p_hs, nullptr, DD, 3, DD, 3);

    // 6. LN2: h2 = ln(hs)
    ln_kernel<<<M/8, 256>>>(p_hs, g2, be2, p_h2, p_h216, M);

    // 7. FF1
    gemm_kernel<<<Mtiles*12, 256, GSM_TOTAL>>>(
        p_h216, p_w1t, b1, nullptr,
        nullptr, p_r16, DD, 12, FFD, 2);

    // 8. FF2: out = r @ w2 + b2 + h2
    gemm_kernel<<<Mtiles*3, 256, GSM_TOTAL>>>(
        p_r16, p_w2t, b2, p_h2,
        out, nullptr, FFD, 3, DD, 3);
}